// round 1
// baseline (speedup 1.0000x reference)
#include <cuda_runtime.h>
#include <math.h>
#include <float.h>

#define CEILDIV(a,b) (((a)+(b)-1)/(b))
#define BN_EPS 1e-5f

// ----------------------------------------------------------------------------
// Scratch (device globals; no dynamic allocation allowed)
// ----------------------------------------------------------------------------
__device__ float g_xyz[8*2048*3];
__device__ float g_h1[8*2048*64];
__device__ float g_points[8*2048*64];
__device__ int   g_fpsidx[8*512];
__device__ float g_newxyz[8*512*3];
__device__ float g_newxyz2[8*256*3];
__device__ float g_newpts[8*512*64];        // reused stage2 as 8*256*128
__device__ int   g_knn[8*512*64];           // reused stage2 as 8*256*64
__device__ float g_bufA[8*512*64*128];      // 33.5M floats
__device__ float g_bufB[8*512*64*128];
__device__ float g_pool[8*512*384];         // reused stage2 as 8*256*768
__device__ float g_f0[8*512*128];
__device__ float g_f1[8*256*256];
__device__ float g_pos[8*256*256];
__device__ float g_x[8*256*256];
__device__ float g_xp[8*256*256];
__device__ float g_q[8*256*256];
__device__ float g_v[8*256*256];
__device__ float g_xr[8*256*256];
__device__ float g_attn[8*4*256*256];
__device__ float g_cat[8*256*1280];
__device__ float g_fuse[8*256*1024];
__device__ float g_gmax[8*1024];
__device__ float g_l1[8*512];
__device__ float g_l2[8*256];
__device__ double g_sum[1024];
__device__ double g_sumsq[1024];

// ----------------------------------------------------------------------------
// Generic tiled GEMM: C[r,o] = sum_d A[r,d]*W[o,d] (+bias[o])
// 64x64 tile, 256 threads, 4x4 per thread
// ----------------------------------------------------------------------------
__global__ void gemm_kernel(const float* __restrict__ A, const float* __restrict__ W,
                            const float* __restrict__ bias, float* __restrict__ C,
                            int R, int D, int O) {
    __shared__ float As[64][17];
    __shared__ float Ws[64][17];
    int tid = threadIdx.x;
    int tr = tid >> 4, tc = tid & 15;
    long rowBase = (long)blockIdx.y * 64;
    int colBase = blockIdx.x * 64;
    float acc[4][4] = {};
    for (int k0 = 0; k0 < D; k0 += 16) {
        #pragma unroll
        for (int e = tid; e < 1024; e += 256) {
            int rr = e >> 4, kk = e & 15;
            long ar = rowBase + rr; int ac = k0 + kk;
            As[rr][kk] = (ar < R && ac < D) ? A[ar * D + ac] : 0.f;
            int wr = colBase + rr;
            Ws[rr][kk] = (wr < O && ac < D) ? W[(long)wr * D + ac] : 0.f;
        }
        __syncthreads();
        #pragma unroll
        for (int kk = 0; kk < 16; kk++) {
            float a[4], w[4];
            #pragma unroll
            for (int i = 0; i < 4; i++) a[i] = As[tr + 16*i][kk];
            #pragma unroll
            for (int j = 0; j < 4; j++) w[j] = Ws[tc + 16*j][kk];
            #pragma unroll
            for (int i = 0; i < 4; i++)
                #pragma unroll
                for (int j = 0; j < 4; j++)
                    acc[i][j] += a[i] * w[j];
        }
        __syncthreads();
    }
    #pragma unroll
    for (int i = 0; i < 4; i++) {
        long row = rowBase + tr + 16*i;
        if (row >= R) continue;
        #pragma unroll
        for (int j = 0; j < 4; j++) {
            int col = colBase + tc + 16*j;
            if (col >= O) continue;
            float vv = acc[i][j];
            if (bias) vv += bias[col];
            C[row * O + col] = vv;
        }
    }
}

// ----------------------------------------------------------------------------
// BatchNorm (training mode, per-channel over rows), double accumulation
// ----------------------------------------------------------------------------
__global__ void zero_stats_kernel() {
    int t = threadIdx.x;
    g_sum[t] = 0.0; g_sumsq[t] = 0.0;
}

__global__ void stats_kernel(const float* __restrict__ X, int R, int C, int rpb) {
    int r0 = blockIdx.x * rpb;
    int r1 = r0 + rpb; if (r1 > R) r1 = R;
    int nch = (C + 255) / 256;
    double acc[4], accsq[4];
    for (int k = 0; k < 4; k++) { acc[k] = 0.0; accsq[k] = 0.0; }
    for (int r = r0; r < r1; r++) {
        const float* row = X + (long)r * C;
        for (int k = 0; k < nch; k++) {
            int c = threadIdx.x + k * 256;
            if (c < C) { double v = row[c]; acc[k] += v; accsq[k] += v * v; }
        }
    }
    for (int k = 0; k < nch; k++) {
        int c = threadIdx.x + k * 256;
        if (c < C) { atomicAdd(&g_sum[c], acc[k]); atomicAdd(&g_sumsq[c], accsq[k]); }
    }
}

// act: 0 = relu, 1 = leaky(0.2)
__global__ void bn_apply_kernel(float* __restrict__ X, long total, int C, int R, int act) {
    long t = (long)blockIdx.x * blockDim.x + threadIdx.x;
    if (t >= total) return;
    int c = (int)(t % C);
    double m = g_sum[c] / R;
    double var = g_sumsq[c] / R - m * m;
    if (var < 0.0) var = 0.0;
    float inv = rsqrtf((float)var + BN_EPS);
    float y = (X[t] - (float)m) * inv;
    X[t] = (act == 0) ? fmaxf(y, 0.f) : (y >= 0.f ? y : 0.2f * y);
}

__global__ void bn_small_kernel(float* __restrict__ X, int C, float slope) {
    int c = blockIdx.x * blockDim.x + threadIdx.x;
    if (c >= C) return;
    double s = 0.0, ss = 0.0;
    for (int r = 0; r < 8; r++) { double v = X[r * C + c]; s += v; ss += v * v; }
    double m = s / 8.0;
    double var = ss / 8.0 - m * m;
    if (var < 0.0) var = 0.0;
    float inv = rsqrtf((float)var + BN_EPS);
    for (int r = 0; r < 8; r++) {
        float y = (X[r * C + c] - (float)m) * inv;
        X[r * C + c] = y >= 0.f ? y : slope * y;
    }
}

// ----------------------------------------------------------------------------
// Layout / elementwise helpers
// ----------------------------------------------------------------------------
__global__ void transpose_x_kernel(const float* __restrict__ x, float* __restrict__ xyz) {
    int t = blockIdx.x * 256 + threadIdx.x;
    if (t >= 8 * 2048 * 3) return;
    int c = t % 3; int n = (t / 3) % 2048; int b = t / (3 * 2048);
    xyz[t] = x[((long)b * 3 + c) * 2048 + n];
}

__global__ void gather_kernel(const float* __restrict__ src, const int* __restrict__ idx,
                              float* __restrict__ dst, int S, int N, int D, long total) {
    long t = (long)blockIdx.x * blockDim.x + threadIdx.x;
    if (t >= total) return;
    int c = (int)(t % D); long bs = t / D;
    int b = (int)(bs / S);
    dst[t] = src[((long)b * N + idx[bs]) * D + c];
}

__global__ void build_group_kernel(const float* __restrict__ pts, const float* __restrict__ ctr,
                                   const int* __restrict__ knn, float* __restrict__ out,
                                   int S, int N, int k, int D, long total) {
    long t = (long)blockIdx.x * blockDim.x + threadIdx.x;
    if (t >= total) return;
    int D2 = 2 * D;
    int c = (int)(t % D2); long rem = t / D2;
    int j = (int)(rem % k); long bs = rem / k;
    int b = (int)(bs / S);
    int pi = knn[bs * 64 + j];
    int cc = (c < D) ? c : c - D;
    float ctrv = ctr[bs * D + cc];
    out[t] = (c < D) ? (pts[((long)b * N + pi) * D + c] - ctrv) : ctrv;
}

__global__ void maxpool_kernel(const float* __restrict__ X, float* __restrict__ out,
                               int k, int C, int OC, int off) {
    int bs = blockIdx.x; int c = threadIdx.x;
    const float* p = X + ((long)bs * k) * C + c;
    float m = -FLT_MAX;
    for (int j = 0; j < k; j++) m = fmaxf(m, p[(long)j * C]);
    out[(long)bs * OC + off + c] = m;
}

__global__ void add_kernel(const float* __restrict__ a, const float* __restrict__ b,
                           float* __restrict__ c, long n) {
    long t = (long)blockIdx.x * blockDim.x + threadIdx.x;
    if (t < n) c[t] = a[t] + b[t];
}

__global__ void sub_kernel(const float* __restrict__ a, const float* __restrict__ b,
                           float* __restrict__ c, long n) {
    long t = (long)blockIdx.x * blockDim.x + threadIdx.x;
    if (t < n) c[t] = a[t] - b[t];
}

__global__ void addcat_kernel(const float* __restrict__ xp, const float* __restrict__ u,
                              float* __restrict__ x, float* __restrict__ cat, int layer) {
    int t = blockIdx.x * 256 + threadIdx.x;   // 8*256*256 total
    float v = xp[t] + u[t];
    x[t] = v;
    int c = t & 255; int row = t >> 8;
    cat[(long)row * 1280 + layer * 256 + c] = v;
}

__global__ void catf1_kernel(const float* __restrict__ f1, float* __restrict__ cat) {
    int t = blockIdx.x * 256 + threadIdx.x;
    int c = t & 255; int row = t >> 8;
    cat[(long)row * 1280 + 1024 + c] = f1[t];
}

__global__ void maxn_kernel(const float* __restrict__ X, float* __restrict__ G) {
    int b = blockIdx.x; int c = blockIdx.y * 256 + threadIdx.x;  // C=1024
    float m = -FLT_MAX;
    for (int n = 0; n < 256; n++) m = fmaxf(m, X[((long)b * 256 + n) * 1024 + c]);
    G[b * 1024 + c] = m;
}

// ----------------------------------------------------------------------------
// Farthest point sampling: one block per batch. Matches jax scan semantics:
// output[it] = far BEFORE update; argmax tie -> smallest index.
// ----------------------------------------------------------------------------
__global__ void fps_kernel(const float* __restrict__ xyz, int N, int npoint,
                           int* __restrict__ outIdx) {
    int b = blockIdx.x;
    __shared__ float sx[2048], sy[2048], sz[2048], sd[2048];
    __shared__ float rv[256];
    __shared__ int   ri[256];
    int t = threadIdx.x;
    for (int n = t; n < N; n += 256) {
        sx[n] = xyz[((long)b * N + n) * 3 + 0];
        sy[n] = xyz[((long)b * N + n) * 3 + 1];
        sz[n] = xyz[((long)b * N + n) * 3 + 2];
        sd[n] = 1e10f;
    }
    __syncthreads();
    int far = 0;
    for (int it = 0; it < npoint; it++) {
        if (t == 0) outIdx[b * npoint + it] = far;
        float cx = sx[far], cy = sy[far], cz = sz[far];
        float bestv = -FLT_MAX; int besti = N;
        for (int n = t; n < N; n += 256) {
            float dx = sx[n] - cx, dy = sy[n] - cy, dz = sz[n] - cz;
            float d = dx * dx + dy * dy + dz * dz;
            float dm = fminf(sd[n], d);
            sd[n] = dm;
            if (dm > bestv) { bestv = dm; besti = n; }
        }
        rv[t] = bestv; ri[t] = besti;
        __syncthreads();
        for (int s = 128; s > 0; s >>= 1) {
            if (t < s) {
                float ov = rv[t + s]; int oi = ri[t + s];
                if (ov > rv[t] || (ov == rv[t] && oi < ri[t])) { rv[t] = ov; ri[t] = oi; }
            }
            __syncthreads();
        }
        far = ri[0];
        __syncthreads();
    }
}

// ----------------------------------------------------------------------------
// kNN: per (b,s) block; distances in shared; kmax=64 sequential argmins
// (matches lax.top_k(-d) ordering incl. index tie-break)
// ----------------------------------------------------------------------------
__global__ void knn_kernel(const float* __restrict__ centers, const float* __restrict__ xyz,
                           int S, int N, int* __restrict__ knnOut) {
    int bs = blockIdx.x; int b = bs / S;
    __shared__ float sd[2048];
    __shared__ float rv[256];
    __shared__ int   ri[256];
    int t = threadIdx.x;
    float cx = centers[(long)bs * 3 + 0];
    float cy = centers[(long)bs * 3 + 1];
    float cz = centers[(long)bs * 3 + 2];
    float cn = cx * cx + cy * cy + cz * cz;
    for (int n = t; n < N; n += 256) {
        float px = xyz[((long)b * N + n) * 3 + 0];
        float py = xyz[((long)b * N + n) * 3 + 1];
        float pz = xyz[((long)b * N + n) * 3 + 2];
        float pn = px * px + py * py + pz * pz;
        float dot = cx * px + cy * py + cz * pz;
        sd[n] = cn + pn - 2.f * dot;
    }
    __syncthreads();
    for (int j = 0; j < 64; j++) {
        float bestv = FLT_MAX; int besti = N;
        for (int n = t; n < N; n += 256) {
            float v = sd[n];
            if (v < bestv) { bestv = v; besti = n; }
        }
        rv[t] = bestv; ri[t] = besti;
        __syncthreads();
        for (int s = 128; s > 0; s >>= 1) {
            if (t < s) {
                float ov = rv[t + s]; int oi = ri[t + s];
                if (ov < rv[t] || (ov == rv[t] && oi < ri[t])) { rv[t] = ov; ri[t] = oi; }
            }
            __syncthreads();
        }
        int sel = ri[0];
        if (t == 0) { knnOut[(long)bs * 64 + j] = sel; sd[sel] = FLT_MAX; }
        __syncthreads();
    }
}

// ----------------------------------------------------------------------------
// Attention. NOTE the reference's reshape quirk:
//   q = proj([b,n,c]).reshape(b,4,n,64)  -> splits the POSITION axis:
//     q[b,h,i,d] = Q[b, h*64 + i/4, (i%4)*64 + d]
//   k,v = proj([b,o,n]).reshape(b,4,64,n) -> splits the channel axis:
//     k[b,h,d,j] = Q[b_row j][h*64 + d]
// ----------------------------------------------------------------------------
__global__ void gram_kernel(const float* __restrict__ Q, float* __restrict__ A) {
    int bh = blockIdx.z; int b = bh >> 2; int h = bh & 3;
    int i0 = blockIdx.y * 16, j0 = blockIdx.x * 16;
    __shared__ float Qi[16][65];
    __shared__ float Qj[16][65];
    int tid = threadIdx.x;
    for (int e = tid; e < 1024; e += 256) {
        int r = e >> 6, d = e & 63;
        int i = i0 + r;
        Qi[r][d] = Q[((long)b * 256 + h * 64 + (i >> 2)) * 256 + (i & 3) * 64 + d];
        Qj[r][d] = Q[((long)b * 256 + j0 + r) * 256 + h * 64 + d];
    }
    __syncthreads();
    int ti = tid >> 4, tj = tid & 15;
    float acc = 0.f;
    #pragma unroll
    for (int d = 0; d < 64; d++) acc += Qi[ti][d] * Qj[tj][d];
    A[((long)bh * 256 + (i0 + ti)) * 256 + (j0 + tj)] = acc;
}

__global__ void softmax_row_kernel(float* __restrict__ A) {
    __shared__ float red[256];
    long row = blockIdx.x;
    float* p = A + row * 256;
    int t = threadIdx.x;
    float v = p[t];
    red[t] = v; __syncthreads();
    for (int s = 128; s > 0; s >>= 1) { if (t < s) red[t] = fmaxf(red[t], red[t + s]); __syncthreads(); }
    float m = red[0]; __syncthreads();
    float e = expf(v - m);
    red[t] = e; __syncthreads();
    for (int s = 128; s > 0; s >>= 1) { if (t < s) red[t] += red[t + s]; __syncthreads(); }
    p[t] = e / red[0];
}

__global__ void softmax_col_kernel(float* __restrict__ A) {
    __shared__ float red[256];
    int bh = blockIdx.x >> 8; int j = blockIdx.x & 255;
    float* base = A + ((long)bh * 256) * 256 + j;
    int t = threadIdx.x;
    float v = base[(long)t * 256];
    red[t] = v; __syncthreads();
    for (int s = 128; s > 0; s >>= 1) { if (t < s) red[t] = fmaxf(red[t], red[t + s]); __syncthreads(); }
    float m = red[0]; __syncthreads();
    float e = expf(v - m);
    red[t] = e; __syncthreads();
    for (int s = 128; s > 0; s >>= 1) { if (t < s) red[t] += red[t + s]; __syncthreads(); }
    base[(long)t * 256] = e / red[0];
}

// XR[b*256+i][c] = sum_j V[b*256+j][c] * A2[b,h(c),j,i]
__global__ void xr_kernel(const float* __restrict__ V, const float* __restrict__ A2,
                          float* __restrict__ XR) {
    int row = blockIdx.x;           // b*256 + i
    int b = row >> 8; int i = row & 255;
    int c = threadIdx.x; int h = c >> 6;
    const float* a = A2 + (((long)(b * 4 + h)) * 256) * 256 + i;  // [j*256]
    const float* v = V + ((long)b * 256) * 256 + c;               // [j*256]
    float acc = 0.f;
    for (int j = 0; j < 256; j++) acc += v[(long)j * 256] * a[(long)j * 256];
    XR[(long)row * 256 + c] = acc;
}

// ----------------------------------------------------------------------------
// Host orchestration
// ----------------------------------------------------------------------------
static void gemm(const float* A, const float* W, const float* bias, float* C,
                 int R, int D, int O) {
    dim3 grid(CEILDIV(O, 64), CEILDIV(R, 64));
    gemm_kernel<<<grid, 256>>>(A, W, bias, C, R, D, O);
}

static void bn(float* X, int R, int C, int act) {
    zero_stats_kernel<<<1, 1024>>>();
    int rpb = CEILDIV(R, 1024); if (rpb < 1) rpb = 1;
    int grid = CEILDIV(R, rpb);
    stats_kernel<<<grid, 256>>>(X, R, C, rpb);
    long total = (long)R * C;
    bn_apply_kernel<<<(int)CEILDIV(total, 256), 256>>>(X, total, C, R, act);
}

extern "C" void kernel_launch(void* const* d_in, const int* in_sizes, int n_in,
                              void* d_out, int out_size) {
    const float* x       = (const float*)d_in[0];
    const float* conv1_w = (const float*)d_in[1];
    const float* conv2_w = (const float*)d_in[2];
    const float* g0_w1   = (const float*)d_in[3];
    const float* g0_w2   = (const float*)d_in[4];
    const float* g0_wc   = (const float*)d_in[5];
    const float* g1_w1   = (const float*)d_in[6];
    const float* g1_w2   = (const float*)d_in[7];
    const float* g1_wc   = (const float*)d_in[8];
    const float* pt_w    = (const float*)d_in[9];
    const float* pos_w   = (const float*)d_in[10];
    const float* pos_b   = (const float*)d_in[11];
    const float* sa_wqk  = (const float*)d_in[12];
    const float* sa_wv   = (const float*)d_in[13];
    const float* sa_bv   = (const float*)d_in[14];
    const float* sa_wt   = (const float*)d_in[15];
    const float* sa_bt   = (const float*)d_in[16];
    const float* fuse_w  = (const float*)d_in[17];
    const float* lin1_w  = (const float*)d_in[18];
    const float* lin2_w  = (const float*)d_in[19];
    const float* lin2_b  = (const float*)d_in[20];
    const float* lin3_w  = (const float*)d_in[21];
    const float* lin3_b  = (const float*)d_in[22];
    float* out = (float*)d_out;

    float *xyz, *h1, *points, *newxyz, *newxyz2, *newpts, *bufA, *bufB, *pool, *f0, *f1;
    float *pos, *xx, *xp, *qb, *vb, *xrb, *attn, *catb, *fuseb, *gmax, *l1, *l2;
    int *fpsidx, *knn;
    cudaGetSymbolAddress((void**)&xyz, g_xyz);
    cudaGetSymbolAddress((void**)&h1, g_h1);
    cudaGetSymbolAddress((void**)&points, g_points);
    cudaGetSymbolAddress((void**)&fpsidx, g_fpsidx);
    cudaGetSymbolAddress((void**)&newxyz, g_newxyz);
    cudaGetSymbolAddress((void**)&newxyz2, g_newxyz2);
    cudaGetSymbolAddress((void**)&newpts, g_newpts);
    cudaGetSymbolAddress((void**)&knn, g_knn);
    cudaGetSymbolAddress((void**)&bufA, g_bufA);
    cudaGetSymbolAddress((void**)&bufB, g_bufB);
    cudaGetSymbolAddress((void**)&pool, g_pool);
    cudaGetSymbolAddress((void**)&f0, g_f0);
    cudaGetSymbolAddress((void**)&f1, g_f1);
    cudaGetSymbolAddress((void**)&pos, g_pos);
    cudaGetSymbolAddress((void**)&xx, g_x);
    cudaGetSymbolAddress((void**)&xp, g_xp);
    cudaGetSymbolAddress((void**)&qb, g_q);
    cudaGetSymbolAddress((void**)&vb, g_v);
    cudaGetSymbolAddress((void**)&xrb, g_xr);
    cudaGetSymbolAddress((void**)&attn, g_attn);
    cudaGetSymbolAddress((void**)&catb, g_cat);
    cudaGetSymbolAddress((void**)&fuseb, g_fuse);
    cudaGetSymbolAddress((void**)&gmax, g_gmax);
    cudaGetSymbolAddress((void**)&l1, g_l1);
    cudaGetSymbolAddress((void**)&l2, g_l2);

    // ---- Stage A: input transpose + conv1/conv2 (+BN,ReLU) ----
    transpose_x_kernel<<<CEILDIV(8*2048*3, 256), 256>>>(x, xyz);
    gemm(xyz, conv1_w, nullptr, h1, 16384, 3, 64);
    bn(h1, 16384, 64, 0);
    gemm(h1, conv2_w, nullptr, points, 16384, 64, 64);
    bn(points, 16384, 64, 0);

    // ---- Stage B: FPS(512) + gather + kNN(64) over 2048 pts ----
    fps_kernel<<<8, 256>>>(xyz, 2048, 512, fpsidx);
    gather_kernel<<<CEILDIV(8*512*3, 256), 256>>>(xyz, fpsidx, newxyz, 512, 2048, 3, 8L*512*3);
    gather_kernel<<<CEILDIV(8*512*64, 256), 256>>>(points, fpsidx, newpts, 512, 2048, 64, 8L*512*64);
    knn_kernel<<<8*512, 256>>>(newxyz, xyz, 512, 2048, knn);

    // ---- Stage C: local_op 0 (3 scales) ----
    {
        const int ks[3] = {16, 32, 64};
        for (int si = 0; si < 3; si++) {
            int k = ks[si];
            long R = 8L * 512 * k;
            long total = R * 128;
            build_group_kernel<<<(int)CEILDIV(total, 256), 256>>>(points, newpts, knn, bufA,
                                                                  512, 2048, k, 64, total);
            gemm(bufA, g0_w1, nullptr, bufB, (int)R, 128, 128);
            bn(bufB, (int)R, 128, 0);
            gemm(bufB, g0_w2, nullptr, bufA, (int)R, 128, 128);
            bn(bufA, (int)R, 128, 0);
            maxpool_kernel<<<4096, 128>>>(bufA, pool, k, 128, 384, si * 128);
        }
        gemm(pool, g0_wc, nullptr, f0, 4096, 384, 128);
        bn(f0, 4096, 128, 0);
    }

    // ---- Stage D: FPS(256) + gather + kNN over 512 centers ----
    fps_kernel<<<8, 256>>>(newxyz, 512, 256, fpsidx);
    gather_kernel<<<CEILDIV(8*256*3, 256), 256>>>(newxyz, fpsidx, newxyz2, 256, 512, 3, 8L*256*3);
    gather_kernel<<<CEILDIV(8*256*128, 256), 256>>>(f0, fpsidx, newpts, 256, 512, 128, 8L*256*128);
    knn_kernel<<<8*256, 256>>>(newxyz2, newxyz, 256, 512, knn);

    // ---- Stage E: local_op 1 (3 scales) -> f1 [8*256, 256] ----
    {
        const int ks[3] = {16, 32, 64};
        for (int si = 0; si < 3; si++) {
            int k = ks[si];
            long R = 8L * 256 * k;
            long total = R * 256;
            build_group_kernel<<<(int)CEILDIV(total, 256), 256>>>(f0, newpts, knn, bufA,
                                                                  256, 512, k, 128, total);
            gemm(bufA, g1_w1, nullptr, bufB, (int)R, 256, 256);
            bn(bufB, (int)R, 256, 0);
            gemm(bufB, g1_w2, nullptr, bufA, (int)R, 256, 256);
            bn(bufA, (int)R, 256, 0);
            maxpool_kernel<<<2048, 256>>>(bufA, pool, k, 256, 768, si * 256);
        }
        gemm(pool, g1_wc, nullptr, f1, 2048, 768, 256);
        bn(f1, 2048, 256, 0);
    }

    // ---- Stage F: pos embedding + pt conv ----
    gemm(newxyz2, pos_w, pos_b, pos, 2048, 3, 256);
    gemm(f1, pt_w, nullptr, xx, 2048, 256, 256);
    bn(xx, 2048, 256, 0);

    // ---- Stage G: 4 offset self-attention layers ----
    for (int i = 0; i < 4; i++) {
        add_kernel<<<2048, 256>>>(xx, pos, xp, 8L*256*256);
        gemm(xp, sa_wqk + (long)i * 256 * 256, nullptr, qb, 2048, 256, 256);
        gemm(xp, sa_wv + (long)i * 256 * 256, sa_bv + i * 256, vb, 2048, 256, 256);
        gram_kernel<<<dim3(16, 16, 32), 256>>>(qb, attn);
        softmax_row_kernel<<<8192, 256>>>(attn);
        softmax_col_kernel<<<8192, 256>>>(attn);
        xr_kernel<<<2048, 256>>>(vb, attn, xrb);
        sub_kernel<<<2048, 256>>>(xp, xrb, xrb, 8L*256*256);
        gemm(xrb, sa_wt + (long)i * 256 * 256, sa_bt + i * 256, qb, 2048, 256, 256);
        bn(qb, 2048, 256, 0);
        addcat_kernel<<<2048, 256>>>(xp, qb, xx, catb, i);
    }
    catf1_kernel<<<2048, 256>>>(f1, catb);

    // ---- Stage H: fuse conv + global max + MLP head ----
    gemm(catb, fuse_w, nullptr, fuseb, 2048, 1280, 1024);
    bn(fuseb, 2048, 1024, 1);
    maxn_kernel<<<dim3(8, 4), 256>>>(fuseb, gmax);
    gemm(gmax, lin1_w, nullptr, l1, 8, 1024, 512);
    bn_small_kernel<<<2, 256>>>(l1, 512, 0.2f);
    gemm(l1, lin2_w, lin2_b, l2, 8, 512, 256);
    bn_small_kernel<<<1, 256>>>(l2, 256, 0.2f);
    gemm(l2, lin3_w, lin3_b, out, 8, 256, 40);
}

// round 2
// speedup vs baseline: 1.2791x; 1.2791x over previous
#include <cuda_runtime.h>
#include <math.h>
#include <float.h>

#define CEILDIV(a,b) (((a)+(b)-1)/(b))
#define BN_EPS 1e-5f

// ----------------------------------------------------------------------------
// Scratch (device globals; no dynamic allocation allowed)
// ----------------------------------------------------------------------------
__device__ float g_xyz[8*2048*3];
__device__ float g_h1[8*2048*64];
__device__ float g_points[8*2048*64];
__device__ int   g_fpsidx[8*512];
__device__ float g_newxyz[8*512*3];
__device__ float g_newxyz2[8*256*3];
__device__ float g_newpts[8*512*64];        // reused stage2 as 8*256*128
__device__ int   g_knn[8*512*64];           // reused stage2 as 8*256*64
__device__ float g_bufA[8*512*64*128];      // 33.5M floats
__device__ float g_bufB[8*512*64*128];
__device__ float g_pool[8*512*384];         // reused stage2 as 8*256*768
__device__ float g_f0[8*512*128];
__device__ float g_f1[8*256*256];
__device__ float g_pos[8*256*256];
__device__ float g_x[8*256*256];
__device__ float g_xp[8*256*256];
__device__ float g_q[8*256*256];
__device__ float g_v[8*256*256];
__device__ float g_xr[8*256*256];
__device__ float g_attn[8*4*256*256];
__device__ float g_cat[8*256*1280];
__device__ float g_fuse[8*256*1024];
__device__ float g_gmax[8*1024];
__device__ float g_l1[8*512];
__device__ float g_l2[8*256];
__device__ double g_sum[1024];
__device__ double g_sumsq[1024];

// ----------------------------------------------------------------------------
// 128x128 tiled GEMM: C[r,o] = sum_d A'[r,d]*W[o,d] (+bias[o])
// where A' = A optionally batchnormed (per-column, stats in g_sum/g_sumsq) + relu.
// 256 threads, 8x8 per thread, k-tile 16, float4 everywhere.
// Requires: R % 128 == 0, D % 16 == 0, O % 8 == 0 (cols beyond O guarded).
// ----------------------------------------------------------------------------
__global__ void gemm128_kernel(const float* __restrict__ A, const float* __restrict__ W,
                               const float* __restrict__ bias, float* __restrict__ C,
                               int R, int D, int O, int useStats, int statN) {
    __shared__ float As[16][132];
    __shared__ float Ws[16][132];
    __shared__ float sM[256];
    __shared__ float sI[256];
    int tid = threadIdx.x;
    if (useStats) {
        for (int c = tid; c < D; c += 256) {
            double m = g_sum[c] / statN;
            double var = g_sumsq[c] / statN - m * m;
            if (var < 0.0) var = 0.0;
            sM[c] = (float)m;
            sI[c] = rsqrtf((float)var + BN_EPS);
        }
        __syncthreads();
    }
    long rowBase = (long)blockIdx.y * 128;
    int colBase = blockIdx.x * 128;
    int tr = tid >> 4, tc = tid & 15;
    int lrow = tid >> 2;          // 0..63
    int lkq = tid & 3;            // float4 slot in k
    float acc[8][8];
    #pragma unroll
    for (int i = 0; i < 8; i++)
        #pragma unroll
        for (int j = 0; j < 8; j++) acc[i][j] = 0.f;

    for (int k0 = 0; k0 < D; k0 += 16) {
        #pragma unroll
        for (int half = 0; half < 2; half++) {
            int row = lrow + 64 * half;
            int kc = k0 + lkq * 4;
            // A tile
            float4 av = *(const float4*)(A + (rowBase + row) * D + kc);
            if (useStats) {
                av.x = fmaxf((av.x - sM[kc + 0]) * sI[kc + 0], 0.f);
                av.y = fmaxf((av.y - sM[kc + 1]) * sI[kc + 1], 0.f);
                av.z = fmaxf((av.z - sM[kc + 2]) * sI[kc + 2], 0.f);
                av.w = fmaxf((av.w - sM[kc + 3]) * sI[kc + 3], 0.f);
            }
            As[lkq * 4 + 0][row] = av.x;
            As[lkq * 4 + 1][row] = av.y;
            As[lkq * 4 + 2][row] = av.z;
            As[lkq * 4 + 3][row] = av.w;
            // W tile
            int wr = colBase + row;
            float4 wv = make_float4(0.f, 0.f, 0.f, 0.f);
            if (wr < O) wv = *(const float4*)(W + (long)wr * D + kc);
            Ws[lkq * 4 + 0][row] = wv.x;
            Ws[lkq * 4 + 1][row] = wv.y;
            Ws[lkq * 4 + 2][row] = wv.z;
            Ws[lkq * 4 + 3][row] = wv.w;
        }
        __syncthreads();
        #pragma unroll
        for (int kk = 0; kk < 16; kk++) {
            float a[8], w[8];
            *(float4*)(a + 0) = *(const float4*)&As[kk][tr * 8 + 0];
            *(float4*)(a + 4) = *(const float4*)&As[kk][tr * 8 + 4];
            *(float4*)(w + 0) = *(const float4*)&Ws[kk][tc * 8 + 0];
            *(float4*)(w + 4) = *(const float4*)&Ws[kk][tc * 8 + 4];
            #pragma unroll
            for (int i = 0; i < 8; i++)
                #pragma unroll
                for (int j = 0; j < 8; j++)
                    acc[i][j] += a[i] * w[j];
        }
        __syncthreads();
    }
    #pragma unroll
    for (int i = 0; i < 8; i++) {
        long row = rowBase + tr * 8 + i;
        int col0 = colBase + tc * 8;
        if (col0 >= O) continue;
        float b0 = 0, b1 = 0, b2 = 0, b3 = 0, b4 = 0, b5 = 0, b6 = 0, b7 = 0;
        if (bias) {
            b0 = bias[col0 + 0]; b1 = bias[col0 + 1]; b2 = bias[col0 + 2]; b3 = bias[col0 + 3];
            b4 = bias[col0 + 4]; b5 = bias[col0 + 5]; b6 = bias[col0 + 6]; b7 = bias[col0 + 7];
        }
        float4 v0 = make_float4(acc[i][0] + b0, acc[i][1] + b1, acc[i][2] + b2, acc[i][3] + b3);
        float4 v1 = make_float4(acc[i][4] + b4, acc[i][5] + b5, acc[i][6] + b6, acc[i][7] + b7);
        *(float4*)(C + row * O + col0) = v0;
        *(float4*)(C + row * O + col0 + 4) = v1;
    }
}

// ----------------------------------------------------------------------------
// Generic fallback GEMM (odd shapes): 64x64 tile, 256 threads, 4x4 per thread
// ----------------------------------------------------------------------------
__global__ void gemm_kernel(const float* __restrict__ A, const float* __restrict__ W,
                            const float* __restrict__ bias, float* __restrict__ C,
                            int R, int D, int O) {
    __shared__ float As[64][17];
    __shared__ float Ws[64][17];
    int tid = threadIdx.x;
    int tr = tid >> 4, tc = tid & 15;
    long rowBase = (long)blockIdx.y * 64;
    int colBase = blockIdx.x * 64;
    float acc[4][4] = {};
    for (int k0 = 0; k0 < D; k0 += 16) {
        #pragma unroll
        for (int e = tid; e < 1024; e += 256) {
            int rr = e >> 4, kk = e & 15;
            long ar = rowBase + rr; int ac = k0 + kk;
            As[rr][kk] = (ar < R && ac < D) ? A[ar * D + ac] : 0.f;
            int wr = colBase + rr;
            Ws[rr][kk] = (wr < O && ac < D) ? W[(long)wr * D + ac] : 0.f;
        }
        __syncthreads();
        #pragma unroll
        for (int kk = 0; kk < 16; kk++) {
            float a[4], w[4];
            #pragma unroll
            for (int i = 0; i < 4; i++) a[i] = As[tr + 16*i][kk];
            #pragma unroll
            for (int j = 0; j < 4; j++) w[j] = Ws[tc + 16*j][kk];
            #pragma unroll
            for (int i = 0; i < 4; i++)
                #pragma unroll
                for (int j = 0; j < 4; j++)
                    acc[i][j] += a[i] * w[j];
        }
        __syncthreads();
    }
    #pragma unroll
    for (int i = 0; i < 4; i++) {
        long row = rowBase + tr + 16*i;
        if (row >= R) continue;
        #pragma unroll
        for (int j = 0; j < 4; j++) {
            int col = colBase + tc + 16*j;
            if (col >= O) continue;
            float vv = acc[i][j];
            if (bias) vv += bias[col];
            C[row * O + col] = vv;
        }
    }
}

// ----------------------------------------------------------------------------
// BatchNorm stats (training mode, per-channel over rows), double accumulation
// ----------------------------------------------------------------------------
__global__ void zero_stats_kernel() {
    int t = threadIdx.x;
    g_sum[t] = 0.0; g_sumsq[t] = 0.0;
}

__global__ void stats_kernel(const float* __restrict__ X, int R, int C, int rpb) {
    int r0 = blockIdx.x * rpb;
    int r1 = r0 + rpb; if (r1 > R) r1 = R;
    int nch = (C + 255) / 256;
    double acc[4], accsq[4];
    for (int k = 0; k < 4; k++) { acc[k] = 0.0; accsq[k] = 0.0; }
    for (int r = r0; r < r1; r++) {
        const float* row = X + (long)r * C;
        for (int k = 0; k < nch; k++) {
            int c = threadIdx.x + k * 256;
            if (c < C) { double v = row[c]; acc[k] += v; accsq[k] += v * v; }
        }
    }
    for (int k = 0; k < nch; k++) {
        int c = threadIdx.x + k * 256;
        if (c < C) { atomicAdd(&g_sum[c], acc[k]); atomicAdd(&g_sumsq[c], accsq[k]); }
    }
}

// act: 0 = relu, 1 = leaky(0.2)
__global__ void bn_apply_kernel(float* __restrict__ X, long total, int C, int R, int act) {
    long t = (long)blockIdx.x * blockDim.x + threadIdx.x;
    if (t >= total) return;
    int c = (int)(t % C);
    double m = g_sum[c] / R;
    double var = g_sumsq[c] / R - m * m;
    if (var < 0.0) var = 0.0;
    float inv = rsqrtf((float)var + BN_EPS);
    float y = (X[t] - (float)m) * inv;
    X[t] = (act == 0) ? fmaxf(y, 0.f) : (y >= 0.f ? y : 0.2f * y);
}

__global__ void bn_small_kernel(float* __restrict__ X, int C, float slope) {
    int c = blockIdx.x * blockDim.x + threadIdx.x;
    if (c >= C) return;
    double s = 0.0, ss = 0.0;
    for (int r = 0; r < 8; r++) { double v = X[r * C + c]; s += v; ss += v * v; }
    double m = s / 8.0;
    double var = ss / 8.0 - m * m;
    if (var < 0.0) var = 0.0;
    float inv = rsqrtf((float)var + BN_EPS);
    for (int r = 0; r < 8; r++) {
        float y = (X[r * C + c] - (float)m) * inv;
        X[r * C + c] = y >= 0.f ? y : slope * y;
    }
}

// ----------------------------------------------------------------------------
// Layout / elementwise helpers
// ----------------------------------------------------------------------------
__global__ void transpose_x_kernel(const float* __restrict__ x, float* __restrict__ xyz) {
    int t = blockIdx.x * 256 + threadIdx.x;
    if (t >= 8 * 2048 * 3) return;
    int c = t % 3; int n = (t / 3) % 2048; int b = t / (3 * 2048);
    xyz[t] = x[((long)b * 3 + c) * 2048 + n];
}

__global__ void gather_kernel(const float* __restrict__ src, const int* __restrict__ idx,
                              float* __restrict__ dst, int S, int N, int D, long total) {
    long t = (long)blockIdx.x * blockDim.x + threadIdx.x;
    if (t >= total) return;
    int c = (int)(t % D); long bs = t / D;
    int b = (int)(bs / S);
    dst[t] = src[((long)b * N + idx[bs]) * D + c];
}

__global__ void build_group_kernel(const float* __restrict__ pts, const float* __restrict__ ctr,
                                   const int* __restrict__ knn, float* __restrict__ out,
                                   int S, int N, int k, int D, long total) {
    long t = (long)blockIdx.x * blockDim.x + threadIdx.x;
    if (t >= total) return;
    int D2 = 2 * D;
    int c = (int)(t % D2); long rem = t / D2;
    int j = (int)(rem % k); long bs = rem / k;
    int b = (int)(bs / S);
    int pi = knn[bs * 64 + j];
    int cc = (c < D) ? c : c - D;
    float ctrv = ctr[bs * D + cc];
    out[t] = (c < D) ? (pts[((long)b * N + pi) * D + c] - ctrv) : ctrv;
}

// maxpool with BN(stats in g_sum/g_sumsq) + relu fused on read
__global__ void maxpool_bn_kernel(const float* __restrict__ X, float* __restrict__ out,
                                  int k, int C, int OC, int off, int statN) {
    int bs = blockIdx.x; int c = threadIdx.x;
    double m = g_sum[c] / statN;
    double var = g_sumsq[c] / statN - m * m;
    if (var < 0.0) var = 0.0;
    float fm = (float)m;
    float fi = rsqrtf((float)var + BN_EPS);
    const float* p = X + ((long)bs * k) * C + c;
    float mx = -FLT_MAX;
    for (int j = 0; j < k; j++) mx = fmaxf(mx, (p[(long)j * C] - fm) * fi);
    out[(long)bs * OC + off + c] = fmaxf(mx, 0.f);
}

__global__ void add_kernel(const float* __restrict__ a, const float* __restrict__ b,
                           float* __restrict__ c, long n) {
    long t = (long)blockIdx.x * blockDim.x + threadIdx.x;
    if (t < n) c[t] = a[t] + b[t];
}

__global__ void sub_kernel(const float* __restrict__ a, const float* __restrict__ b,
                           float* __restrict__ c, long n) {
    long t = (long)blockIdx.x * blockDim.x + threadIdx.x;
    if (t < n) c[t] = a[t] - b[t];
}

__global__ void addcat_kernel(const float* __restrict__ xp, const float* __restrict__ u,
                              float* __restrict__ x, float* __restrict__ cat, int layer) {
    int t = blockIdx.x * 256 + threadIdx.x;   // 8*256*256 total
    float v = xp[t] + u[t];
    x[t] = v;
    int c = t & 255; int row = t >> 8;
    cat[(long)row * 1280 + layer * 256 + c] = v;
}

__global__ void catf1_kernel(const float* __restrict__ f1, float* __restrict__ cat) {
    int t = blockIdx.x * 256 + threadIdx.x;
    int c = t & 255; int row = t >> 8;
    cat[(long)row * 1280 + 1024 + c] = f1[t];
}

__global__ void maxn_kernel(const float* __restrict__ X, float* __restrict__ G) {
    int b = blockIdx.x; int c = blockIdx.y * 256 + threadIdx.x;  // C=1024
    float m = -FLT_MAX;
    for (int n = 0; n < 256; n++) m = fmaxf(m, X[((long)b * 256 + n) * 1024 + c]);
    G[b * 1024 + c] = m;
}

// ----------------------------------------------------------------------------
// Farthest point sampling: one block per batch; matches jax scan semantics.
// ----------------------------------------------------------------------------
__global__ void fps_kernel(const float* __restrict__ xyz, int N, int npoint,
                           int* __restrict__ outIdx) {
    int b = blockIdx.x;
    __shared__ float sx[2048], sy[2048], sz[2048], sd[2048];
    __shared__ float rv[256];
    __shared__ int   ri[256];
    int t = threadIdx.x;
    for (int n = t; n < N; n += 256) {
        sx[n] = xyz[((long)b * N + n) * 3 + 0];
        sy[n] = xyz[((long)b * N + n) * 3 + 1];
        sz[n] = xyz[((long)b * N + n) * 3 + 2];
        sd[n] = 1e10f;
    }
    __syncthreads();
    int far = 0;
    for (int it = 0; it < npoint; it++) {
        if (t == 0) outIdx[b * npoint + it] = far;
        float cx = sx[far], cy = sy[far], cz = sz[far];
        float bestv = -FLT_MAX; int besti = N;
        for (int n = t; n < N; n += 256) {
            float dx = sx[n] - cx, dy = sy[n] - cy, dz = sz[n] - cz;
            float d = dx * dx + dy * dy + dz * dz;
            float dm = fminf(sd[n], d);
            sd[n] = dm;
            if (dm > bestv) { bestv = dm; besti = n; }
        }
        rv[t] = bestv; ri[t] = besti;
        __syncthreads();
        for (int s = 128; s > 0; s >>= 1) {
            if (t < s) {
                float ov = rv[t + s]; int oi = ri[t + s];
                if (ov > rv[t] || (ov == rv[t] && oi < ri[t])) { rv[t] = ov; ri[t] = oi; }
            }
            __syncthreads();
        }
        far = ri[0];
        __syncthreads();
    }
}

// ----------------------------------------------------------------------------
// kNN: per (b,s) block; distances in shared; 64 sequential argmins.
// ----------------------------------------------------------------------------
__global__ void knn_kernel(const float* __restrict__ centers, const float* __restrict__ xyz,
                           int S, int N, int* __restrict__ knnOut) {
    int bs = blockIdx.x; int b = bs / S;
    __shared__ float sd[2048];
    __shared__ float rv[256];
    __shared__ int   ri[256];
    int t = threadIdx.x;
    float cx = centers[(long)bs * 3 + 0];
    float cy = centers[(long)bs * 3 + 1];
    float cz = centers[(long)bs * 3 + 2];
    float cn = cx * cx + cy * cy + cz * cz;
    for (int n = t; n < N; n += 256) {
        float px = xyz[((long)b * N + n) * 3 + 0];
        float py = xyz[((long)b * N + n) * 3 + 1];
        float pz = xyz[((long)b * N + n) * 3 + 2];
        float pn = px * px + py * py + pz * pz;
        float dot = cx * px + cy * py + cz * pz;
        sd[n] = cn + pn - 2.f * dot;
    }
    __syncthreads();
    for (int j = 0; j < 64; j++) {
        float bestv = FLT_MAX; int besti = N;
        for (int n = t; n < N; n += 256) {
            float v = sd[n];
            if (v < bestv) { bestv = v; besti = n; }
        }
        rv[t] = bestv; ri[t] = besti;
        __syncthreads();
        for (int s = 128; s > 0; s >>= 1) {
            if (t < s) {
                float ov = rv[t + s]; int oi = ri[t + s];
                if (ov < rv[t] || (ov == rv[t] && oi < ri[t])) { rv[t] = ov; ri[t] = oi; }
            }
            __syncthreads();
        }
        int sel = ri[0];
        if (t == 0) { knnOut[(long)bs * 64 + j] = sel; sd[sel] = FLT_MAX; }
        __syncthreads();
    }
}

// ----------------------------------------------------------------------------
// Attention (reference reshape quirk preserved; see R1 notes).
// ----------------------------------------------------------------------------
__global__ void gram_kernel(const float* __restrict__ Q, float* __restrict__ A) {
    int bh = blockIdx.z; int b = bh >> 2; int h = bh & 3;
    int i0 = blockIdx.y * 16, j0 = blockIdx.x * 16;
    __shared__ float Qi[16][65];
    __shared__ float Qj[16][65];
    int tid = threadIdx.x;
    for (int e = tid; e < 1024; e += 256) {
        int r = e >> 6, d = e & 63;
        int i = i0 + r;
        Qi[r][d] = Q[((long)b * 256 + h * 64 + (i >> 2)) * 256 + (i & 3) * 64 + d];
        Qj[r][d] = Q[((long)b * 256 + j0 + r) * 256 + h * 64 + d];
    }
    __syncthreads();
    int ti = tid >> 4, tj = tid & 15;
    float acc = 0.f;
    #pragma unroll
    for (int d = 0; d < 64; d++) acc += Qi[ti][d] * Qj[tj][d];
    A[((long)bh * 256 + (i0 + ti)) * 256 + (j0 + tj)] = acc;
}

__global__ void softmax_row_kernel(float* __restrict__ A) {
    __shared__ float red[256];
    long row = blockIdx.x;
    float* p = A + row * 256;
    int t = threadIdx.x;
    float v = p[t];
    red[t] = v; __syncthreads();
    for (int s = 128; s > 0; s >>= 1) { if (t < s) red[t] = fmaxf(red[t], red[t + s]); __syncthreads(); }
    float m = red[0]; __syncthreads();
    float e = expf(v - m);
    red[t] = e; __syncthreads();
    for (int s = 128; s > 0; s >>= 1) { if (t < s) red[t] += red[t + s]; __syncthreads(); }
    p[t] = e / red[0];
}

__global__ void softmax_col_kernel(float* __restrict__ A) {
    __shared__ float red[256];
    int bh = blockIdx.x >> 8; int j = blockIdx.x & 255;
    float* base = A + ((long)bh * 256) * 256 + j;
    int t = threadIdx.x;
    float v = base[(long)t * 256];
    red[t] = v; __syncthreads();
    for (int s = 128; s > 0; s >>= 1) { if (t < s) red[t] = fmaxf(red[t], red[t + s]); __syncthreads(); }
    float m = red[0]; __syncthreads();
    float e = expf(v - m);
    red[t] = e; __syncthreads();
    for (int s = 128; s > 0; s >>= 1) { if (t < s) red[t] += red[t + s]; __syncthreads(); }
    base[(long)t * 256] = e / red[0];
}

// XR[b*256+i][c] = sum_j V[b*256+j][c] * A2[b,h(c),j,i]
__global__ void xr_kernel(const float* __restrict__ V, const float* __restrict__ A2,
                          float* __restrict__ XR) {
    int row = blockIdx.x;           // b*256 + i
    int b = row >> 8; int i = row & 255;
    int c = threadIdx.x; int h = c >> 6;
    const float* a = A2 + (((long)(b * 4 + h)) * 256) * 256 + i;  // [j*256]
    const float* v = V + ((long)b * 256) * 256 + c;               // [j*256]
    float acc = 0.f;
    for (int j = 0; j < 256; j++) acc += v[(long)j * 256] * a[(long)j * 256];
    XR[(long)row * 256 + c] = acc;
}

// ----------------------------------------------------------------------------
// Host orchestration
// ----------------------------------------------------------------------------
static void gemm_old(const float* A, const float* W, const float* bias, float* C,
                     int R, int D, int O) {
    dim3 grid(CEILDIV(O, 64), CEILDIV(R, 64));
    gemm_kernel<<<grid, 256>>>(A, W, bias, C, R, D, O);
}

static void gemm_big(const float* A, const float* W, const float* bias, float* C,
                     int R, int D, int O, int useStats, int statN) {
    dim3 grid(CEILDIV(O, 128), R / 128);
    gemm128_kernel<<<grid, 256>>>(A, W, bias, C, R, D, O, useStats, statN);
}

static void computeStats(const float* X, int R, int C) {
    zero_stats_kernel<<<1, 1024>>>();
    int rpb = CEILDIV(R, 1024); if (rpb < 1) rpb = 1;
    int grid = CEILDIV(R, rpb);
    stats_kernel<<<grid, 256>>>(X, R, C, rpb);
}

static void applyBN(float* X, int R, int C, int act) {
    long total = (long)R * C;
    bn_apply_kernel<<<(int)CEILDIV(total, 256), 256>>>(X, total, C, R, act);
}

static void bn(float* X, int R, int C, int act) {
    computeStats(X, R, C);
    applyBN(X, R, C, act);
}

extern "C" void kernel_launch(void* const* d_in, const int* in_sizes, int n_in,
                              void* d_out, int out_size) {
    const float* x       = (const float*)d_in[0];
    const float* conv1_w = (const float*)d_in[1];
    const float* conv2_w = (const float*)d_in[2];
    const float* g0_w1   = (const float*)d_in[3];
    const float* g0_w2   = (const float*)d_in[4];
    const float* g0_wc   = (const float*)d_in[5];
    const float* g1_w1   = (const float*)d_in[6];
    const float* g1_w2   = (const float*)d_in[7];
    const float* g1_wc   = (const float*)d_in[8];
    const float* pt_w    = (const float*)d_in[9];
    const float* pos_w   = (const float*)d_in[10];
    const float* pos_b   = (const float*)d_in[11];
    const float* sa_wqk  = (const float*)d_in[12];
    const float* sa_wv   = (const float*)d_in[13];
    const float* sa_bv   = (const float*)d_in[14];
    const float* sa_wt   = (const float*)d_in[15];
    const float* sa_bt   = (const float*)d_in[16];
    const float* fuse_w  = (const float*)d_in[17];
    const float* lin1_w  = (const float*)d_in[18];
    const float* lin2_w  = (const float*)d_in[19];
    const float* lin2_b  = (const float*)d_in[20];
    const float* lin3_w  = (const float*)d_in[21];
    const float* lin3_b  = (const float*)d_in[22];
    float* out = (float*)d_out;

    float *xyz, *h1, *points, *newxyz, *newxyz2, *newpts, *bufA, *bufB, *pool, *f0, *f1;
    float *pos, *xx, *xp, *qb, *vb, *xrb, *attn, *catb, *fuseb, *gmax, *l1, *l2;
    int *fpsidx, *knn;
    cudaGetSymbolAddress((void**)&xyz, g_xyz);
    cudaGetSymbolAddress((void**)&h1, g_h1);
    cudaGetSymbolAddress((void**)&points, g_points);
    cudaGetSymbolAddress((void**)&fpsidx, g_fpsidx);
    cudaGetSymbolAddress((void**)&newxyz, g_newxyz);
    cudaGetSymbolAddress((void**)&newxyz2, g_newxyz2);
    cudaGetSymbolAddress((void**)&newpts, g_newpts);
    cudaGetSymbolAddress((void**)&knn, g_knn);
    cudaGetSymbolAddress((void**)&bufA, g_bufA);
    cudaGetSymbolAddress((void**)&bufB, g_bufB);
    cudaGetSymbolAddress((void**)&pool, g_pool);
    cudaGetSymbolAddress((void**)&f0, g_f0);
    cudaGetSymbolAddress((void**)&f1, g_f1);
    cudaGetSymbolAddress((void**)&pos, g_pos);
    cudaGetSymbolAddress((void**)&xx, g_x);
    cudaGetSymbolAddress((void**)&xp, g_xp);
    cudaGetSymbolAddress((void**)&qb, g_q);
    cudaGetSymbolAddress((void**)&vb, g_v);
    cudaGetSymbolAddress((void**)&xrb, g_xr);
    cudaGetSymbolAddress((void**)&attn, g_attn);
    cudaGetSymbolAddress((void**)&catb, g_cat);
    cudaGetSymbolAddress((void**)&fuseb, g_fuse);
    cudaGetSymbolAddress((void**)&gmax, g_gmax);
    cudaGetSymbolAddress((void**)&l1, g_l1);
    cudaGetSymbolAddress((void**)&l2, g_l2);

    // ---- Stage A: input transpose + conv1/conv2 (+BN,ReLU) ----
    transpose_x_kernel<<<CEILDIV(8*2048*3, 256), 256>>>(x, xyz);
    gemm_old(xyz, conv1_w, nullptr, h1, 16384, 3, 64);
    computeStats(h1, 16384, 64);
    // conv2 consumes h1 with BN+relu applied on load
    gemm_big(h1, conv2_w, nullptr, points, 16384, 64, 64, 1, 16384);
    bn(points, 16384, 64, 0);

    // ---- Stage B: FPS(512) + gather + kNN(64) over 2048 pts ----
    fps_kernel<<<8, 256>>>(xyz, 2048, 512, fpsidx);
    gather_kernel<<<CEILDIV(8*512*3, 256), 256>>>(xyz, fpsidx, newxyz, 512, 2048, 3, 8L*512*3);
    gather_kernel<<<CEILDIV(8*512*64, 256), 256>>>(points, fpsidx, newpts, 512, 2048, 64, 8L*512*64);
    knn_kernel<<<8*512, 256>>>(newxyz, xyz, 512, 2048, knn);

    // ---- Stage C: local_op 0 (3 scales) ----
    {
        const int ks[3] = {16, 32, 64};
        for (int si = 0; si < 3; si++) {
            int k = ks[si];
            int R = 8 * 512 * k;
            long total = (long)R * 128;
            build_group_kernel<<<(int)CEILDIV(total, 256), 256>>>(points, newpts, knn, bufA,
                                                                  512, 2048, k, 64, total);
            gemm_big(bufA, g0_w1, nullptr, bufB, R, 128, 128, 0, 0);
            computeStats(bufB, R, 128);
            gemm_big(bufB, g0_w2, nullptr, bufA, R, 128, 128, 1, R);
            computeStats(bufA, R, 128);
            maxpool_bn_kernel<<<4096, 128>>>(bufA, pool, k, 128, 384, si * 128, R);
        }
        gemm_old(pool, g0_wc, nullptr, f0, 4096, 384, 128);
        bn(f0, 4096, 128, 0);
    }

    // ---- Stage D: FPS(256) + gather + kNN over 512 centers ----
    fps_kernel<<<8, 256>>>(newxyz, 512, 256, fpsidx);
    gather_kernel<<<CEILDIV(8*256*3, 256), 256>>>(newxyz, fpsidx, newxyz2, 256, 512, 3, 8L*256*3);
    gather_kernel<<<CEILDIV(8*256*128, 256), 256>>>(f0, fpsidx, newpts, 256, 512, 128, 8L*256*128);
    knn_kernel<<<8*256, 256>>>(newxyz2, newxyz, 256, 512, knn);

    // ---- Stage E: local_op 1 (3 scales) -> f1 [8*256, 256] ----
    {
        const int ks[3] = {16, 32, 64};
        for (int si = 0; si < 3; si++) {
            int k = ks[si];
            int R = 8 * 256 * k;
            long total = (long)R * 256;
            build_group_kernel<<<(int)CEILDIV(total, 256), 256>>>(f0, newpts, knn, bufA,
                                                                  256, 512, k, 128, total);
            gemm_big(bufA, g1_w1, nullptr, bufB, R, 256, 256, 0, 0);
            computeStats(bufB, R, 256);
            gemm_big(bufB, g1_w2, nullptr, bufA, R, 256, 256, 1, R);
            computeStats(bufA, R, 256);
            maxpool_bn_kernel<<<2048, 256>>>(bufA, pool, k, 256, 768, si * 256, R);
        }
        gemm_big(pool, g1_wc, nullptr, f1, 2048, 768, 256, 0, 0);
        bn(f1, 2048, 256, 0);
    }

    // ---- Stage F: pos embedding + pt conv ----
    gemm_old(newxyz2, pos_w, pos_b, pos, 2048, 3, 256);
    gemm_old(f1, pt_w, nullptr, xx, 2048, 256, 256);
    bn(xx, 2048, 256, 0);

    // ---- Stage G: 4 offset self-attention layers ----
    for (int i = 0; i < 4; i++) {
        add_kernel<<<2048, 256>>>(xx, pos, xp, 8L*256*256);
        gemm_old(xp, sa_wqk + (long)i * 256 * 256, nullptr, qb, 2048, 256, 256);
        gemm_old(xp, sa_wv + (long)i * 256 * 256, sa_bv + i * 256, vb, 2048, 256, 256);
        gram_kernel<<<dim3(16, 16, 32), 256>>>(qb, attn);
        softmax_row_kernel<<<8192, 256>>>(attn);
        softmax_col_kernel<<<8192, 256>>>(attn);
        xr_kernel<<<2048, 256>>>(vb, attn, xrb);
        sub_kernel<<<2048, 256>>>(xp, xrb, xrb, 8L*256*256);
        gemm_old(xrb, sa_wt + (long)i * 256 * 256, sa_bt + i * 256, qb, 2048, 256, 256);
        bn(qb, 2048, 256, 0);
        addcat_kernel<<<2048, 256>>>(xp, qb, xx, catb, i);
    }
    catf1_kernel<<<2048, 256>>>(f1, catb);

    // ---- Stage H: fuse conv + global max + MLP head ----
    gemm_big(catb, fuse_w, nullptr, fuseb, 2048, 1280, 1024, 0, 0);
    bn(fuseb, 2048, 1024, 1);
    maxn_kernel<<<dim3(8, 4), 256>>>(fuseb, gmax);
    gemm_old(gmax, lin1_w, nullptr, l1, 8, 1024, 512);
    bn_small_kernel<<<2, 256>>>(l1, 512, 0.2f);
    gemm_old(l1, lin2_w, lin2_b, l2, 8, 512, 256);
    bn_small_kernel<<<1, 256>>>(l2, 256, 0.2f);
    gemm_old(l2, lin3_w, lin3_b, out, 8, 256, 40);
}

// round 3
// speedup vs baseline: 1.8343x; 1.4340x over previous
#include <cuda_runtime.h>
#include <math.h>
#include <float.h>

#define CEILDIV(a,b) (((a)+(b)-1)/(b))
#define BN_EPS 1e-5f

// ----------------------------------------------------------------------------
// Scratch (device globals; no dynamic allocation allowed)
// ----------------------------------------------------------------------------
__device__ float g_xyz[8*2048*3];
__device__ float g_h1[8*2048*64];
__device__ float g_points[8*2048*64];
__device__ int   g_fpsidx[8*512];
__device__ float g_newxyz[8*512*3];
__device__ float g_newxyz2[8*256*3];
__device__ float g_newpts[8*512*64];        // reused stage2 as 8*256*128
__device__ int   g_knn[8*512*64];           // reused stage2 as 8*256*64
__device__ float g_U[16384*128];            // stage C U (16384x128) / stage E U (4096x256)
__device__ float g_V[4096*128];             // stage C V (4096x128) / stage E V (2048x256)
__device__ float g_w1a[256*128];
__device__ float g_w1d[256*128];
__device__ float g_pool[8*512*384];         // reused stage2 as 8*256*768
__device__ float g_f0[8*512*128];
__device__ float g_f1[8*256*256];
__device__ float g_pos[8*256*256];
__device__ float g_x[8*256*256];
__device__ float g_xp[8*256*256];
__device__ float g_q[8*256*256];
__device__ float g_v[8*256*256];
__device__ float g_xr[8*256*256];
__device__ float g_attn[8*4*256*256];
__device__ float g_cat[8*256*1280];
__device__ float g_fuse[8*256*1024];
__device__ float g_gmax[8*1024];
__device__ float g_l1[8*512];
__device__ float g_l2[8*256];
__device__ double g_sum[1024];
__device__ double g_sumsq[1024];
__device__ double g_sum2[1024];
__device__ double g_sumsq2[1024];

// ----------------------------------------------------------------------------
// 128x128 tiled GEMM: C[r,o] = sum_d A'[r,d]*W[o,d] (+bias[o])
// A' = A optionally batchnormed (stats in g_sum/g_sumsq) + relu.
// 256 threads, 8x8 per thread, k-tile 16, float4 loads.
// Requires: R % 128 == 0, D % 16 == 0, O % 8 == 0.
// ----------------------------------------------------------------------------
__global__ void gemm128_kernel(const float* __restrict__ A, const float* __restrict__ W,
                               const float* __restrict__ bias, float* __restrict__ C,
                               int R, int D, int O, int useStats, int statN) {
    __shared__ float As[16][132];
    __shared__ float Ws[16][132];
    __shared__ float sM[256];
    __shared__ float sI[256];
    int tid = threadIdx.x;
    if (useStats) {
        for (int c = tid; c < D; c += 256) {
            double m = g_sum[c] / statN;
            double var = g_sumsq[c] / statN - m * m;
            if (var < 0.0) var = 0.0;
            sM[c] = (float)m;
            sI[c] = rsqrtf((float)var + BN_EPS);
        }
        __syncthreads();
    }
    long rowBase = (long)blockIdx.y * 128;
    int colBase = blockIdx.x * 128;
    int tr = tid >> 4, tc = tid & 15;
    int lrow = tid >> 2;
    int lkq = tid & 3;
    float acc[8][8];
    #pragma unroll
    for (int i = 0; i < 8; i++)
        #pragma unroll
        for (int j = 0; j < 8; j++) acc[i][j] = 0.f;

    for (int k0 = 0; k0 < D; k0 += 16) {
        #pragma unroll
        for (int half = 0; half < 2; half++) {
            int row = lrow + 64 * half;
            int kc = k0 + lkq * 4;
            float4 av = *(const float4*)(A + (rowBase + row) * D + kc);
            if (useStats) {
                av.x = fmaxf((av.x - sM[kc + 0]) * sI[kc + 0], 0.f);
                av.y = fmaxf((av.y - sM[kc + 1]) * sI[kc + 1], 0.f);
                av.z = fmaxf((av.z - sM[kc + 2]) * sI[kc + 2], 0.f);
                av.w = fmaxf((av.w - sM[kc + 3]) * sI[kc + 3], 0.f);
            }
            As[lkq * 4 + 0][row] = av.x;
            As[lkq * 4 + 1][row] = av.y;
            As[lkq * 4 + 2][row] = av.z;
            As[lkq * 4 + 3][row] = av.w;
            int wr = colBase + row;
            float4 wv = make_float4(0.f, 0.f, 0.f, 0.f);
            if (wr < O) wv = *(const float4*)(W + (long)wr * D + kc);
            Ws[lkq * 4 + 0][row] = wv.x;
            Ws[lkq * 4 + 1][row] = wv.y;
            Ws[lkq * 4 + 2][row] = wv.z;
            Ws[lkq * 4 + 3][row] = wv.w;
        }
        __syncthreads();
        #pragma unroll
        for (int kk = 0; kk < 16; kk++) {
            float a[8], w[8];
            *(float4*)(a + 0) = *(const float4*)&As[kk][tr * 8 + 0];
            *(float4*)(a + 4) = *(const float4*)&As[kk][tr * 8 + 4];
            *(float4*)(w + 0) = *(const float4*)&Ws[kk][tc * 8 + 0];
            *(float4*)(w + 4) = *(const float4*)&Ws[kk][tc * 8 + 4];
            #pragma unroll
            for (int i = 0; i < 8; i++)
                #pragma unroll
                for (int j = 0; j < 8; j++)
                    acc[i][j] += a[i] * w[j];
        }
        __syncthreads();
    }
    #pragma unroll
    for (int i = 0; i < 8; i++) {
        long row = rowBase + tr * 8 + i;
        int col0 = colBase + tc * 8;
        if (col0 >= O) continue;
        float b0 = 0, b1 = 0, b2 = 0, b3 = 0, b4 = 0, b5 = 0, b6 = 0, b7 = 0;
        if (bias) {
            b0 = bias[col0 + 0]; b1 = bias[col0 + 1]; b2 = bias[col0 + 2]; b3 = bias[col0 + 3];
            b4 = bias[col0 + 4]; b5 = bias[col0 + 5]; b6 = bias[col0 + 6]; b7 = bias[col0 + 7];
        }
        float4 v0 = make_float4(acc[i][0] + b0, acc[i][1] + b1, acc[i][2] + b2, acc[i][3] + b3);
        float4 v1 = make_float4(acc[i][4] + b4, acc[i][5] + b5, acc[i][6] + b6, acc[i][7] + b7);
        *(float4*)(C + row * O + col0) = v0;
        *(float4*)(C + row * O + col0 + 4) = v1;
    }
}

// ----------------------------------------------------------------------------
// Fused local-op GEMM2:
//   A row r (= s*k + j): a[c] = relu(bn1(U[pidx(s,j)][c] + V[s][c]))   (stats g_sum/g_sumsq)
//   C = A * W2^T, then per-center raw max -> poolOut[s, off+col],
//   and per-channel sum/sumsq of C accumulated into g_sum2/g_sumsq2.
// Grid: (O/128, R/128); R = 8*S*k, k = 1<<kshift, 8 <= k <= 128.
// ----------------------------------------------------------------------------
__global__ void local_gemm2_kernel(const float* __restrict__ U, const float* __restrict__ V,
                                   const int* __restrict__ knn, const float* __restrict__ W,
                                   float* __restrict__ poolOut,
                                   int S, int N, int D, int O, int kshift,
                                   int statN, int OC, int off) {
    __shared__ float As[16][132];
    __shared__ float Ws[16][132];
    __shared__ float sRed[16][132];
    __shared__ float sM[256];
    __shared__ float sI[256];
    __shared__ int sP[128];
    __shared__ int sS[128];
    int tid = threadIdx.x;
    long rowBase = (long)blockIdx.y * 128;
    int colBase = blockIdx.x * 128;

    for (int c = tid; c < D; c += 256) {
        double m = g_sum[c] / statN;
        double var = g_sumsq[c] / statN - m * m;
        if (var < 0.0) var = 0.0;
        sM[c] = (float)m;
        sI[c] = rsqrtf((float)var + BN_EPS);
    }
    if (tid < 128) {
        long grow = rowBase + tid;
        int s = (int)(grow >> kshift);
        int j = (int)(grow & ((1 << kshift) - 1));
        int b = s / S;
        sS[tid] = s;
        sP[tid] = b * N + knn[(long)s * 64 + j];
    }
    __syncthreads();

    int tr = tid >> 4, tc = tid & 15;
    int lrow = tid >> 2;
    int lkq = tid & 3;
    float acc[8][8];
    #pragma unroll
    for (int i = 0; i < 8; i++)
        #pragma unroll
        for (int j = 0; j < 8; j++) acc[i][j] = 0.f;

    for (int k0 = 0; k0 < D; k0 += 16) {
        #pragma unroll
        for (int half = 0; half < 2; half++) {
            int row = lrow + 64 * half;
            int kc = k0 + lkq * 4;
            float4 uv = *(const float4*)(U + (long)sP[row] * D + kc);
            float4 vv = *(const float4*)(V + (long)sS[row] * D + kc);
            float x0 = fmaxf((uv.x + vv.x - sM[kc + 0]) * sI[kc + 0], 0.f);
            float x1 = fmaxf((uv.y + vv.y - sM[kc + 1]) * sI[kc + 1], 0.f);
            float x2 = fmaxf((uv.z + vv.z - sM[kc + 2]) * sI[kc + 2], 0.f);
            float x3 = fmaxf((uv.w + vv.w - sM[kc + 3]) * sI[kc + 3], 0.f);
            As[lkq * 4 + 0][row] = x0;
            As[lkq * 4 + 1][row] = x1;
            As[lkq * 4 + 2][row] = x2;
            As[lkq * 4 + 3][row] = x3;
            float4 wv = *(const float4*)(W + (long)(colBase + row) * D + kc);
            Ws[lkq * 4 + 0][row] = wv.x;
            Ws[lkq * 4 + 1][row] = wv.y;
            Ws[lkq * 4 + 2][row] = wv.z;
            Ws[lkq * 4 + 3][row] = wv.w;
        }
        __syncthreads();
        #pragma unroll
        for (int kk = 0; kk < 16; kk++) {
            float a[8], w[8];
            *(float4*)(a + 0) = *(const float4*)&As[kk][tr * 8 + 0];
            *(float4*)(a + 4) = *(const float4*)&As[kk][tr * 8 + 4];
            *(float4*)(w + 0) = *(const float4*)&Ws[kk][tc * 8 + 0];
            *(float4*)(w + 4) = *(const float4*)&Ws[kk][tc * 8 + 4];
            #pragma unroll
            for (int i = 0; i < 8; i++)
                #pragma unroll
                for (int j = 0; j < 8; j++)
                    acc[i][j] += a[i] * w[j];
        }
        __syncthreads();
    }

    // --- epilogue 1: per-center max -> poolOut ---
    int g = (1 << kshift) >> 3;   // tr-threads per center (2,4,8)
    #pragma unroll
    for (int j = 0; j < 8; j++) {
        float m = acc[0][j];
        #pragma unroll
        for (int i = 1; i < 8; i++) m = fmaxf(m, acc[i][j]);
        sRed[tr][tc * 8 + j] = m;
    }
    __syncthreads();
    if ((tr & (g - 1)) == 0) {
        int s = sS[tr * 8];
        #pragma unroll
        for (int j = 0; j < 8; j++) {
            float m = sRed[tr][tc * 8 + j];
            for (int q = 1; q < g; q++) m = fmaxf(m, sRed[tr + q][tc * 8 + j]);
            poolOut[(long)s * OC + off + colBase + tc * 8 + j] = m;
        }
    }
    __syncthreads();
    // --- epilogue 2: channel sums for BN2 ---
    #pragma unroll
    for (int j = 0; j < 8; j++) {
        float sm = 0.f;
        #pragma unroll
        for (int i = 0; i < 8; i++) sm += acc[i][j];
        sRed[tr][tc * 8 + j] = sm;
    }
    __syncthreads();
    if (tr == 0) {
        #pragma unroll
        for (int j = 0; j < 8; j++) {
            float tot = 0.f;
            for (int q = 0; q < 16; q++) tot += sRed[q][tc * 8 + j];
            atomicAdd(&g_sum2[colBase + tc * 8 + j], (double)tot);
        }
    }
    __syncthreads();
    #pragma unroll
    for (int j = 0; j < 8; j++) {
        float sm = 0.f;
        #pragma unroll
        for (int i = 0; i < 8; i++) sm += acc[i][j] * acc[i][j];
        sRed[tr][tc * 8 + j] = sm;
    }
    __syncthreads();
    if (tr == 0) {
        #pragma unroll
        for (int j = 0; j < 8; j++) {
            float tot = 0.f;
            for (int q = 0; q < 16; q++) tot += sRed[q][tc * 8 + j];
            atomicAdd(&g_sumsq2[colBase + tc * 8 + j], (double)tot);
        }
    }
}

// BN1 stats over layer-1 values (U[idx]+V) for one scale.
__global__ void stats1_kernel(const float* __restrict__ U, const float* __restrict__ V,
                              const int* __restrict__ knn, int S, int N, int C, int k) {
    int s = blockIdx.x;
    int c = threadIdx.x;
    int b = s / S;
    float v = V[(long)s * C + c];
    const int* kn = knn + (long)s * 64;
    float acc = 0.f, accsq = 0.f;
    for (int j = 0; j < k; j++) {
        float u = U[((long)b * N + kn[j]) * C + c];
        float x = u + v;
        acc += x;
        accsq += x * x;
    }
    atomicAdd(&g_sum[c], (double)acc);
    atomicAdd(&g_sumsq[c], (double)accsq);
}

// pool[s, off+c] = relu(bn2(rawmax)) using g_sum2/g_sumsq2
__global__ void pool_finalize_kernel(float* __restrict__ pool, int OC, int off, int statN) {
    int s = blockIdx.x;
    int c = threadIdx.x;
    double m = g_sum2[c] / statN;
    double var = g_sumsq2[c] / statN - m * m;
    if (var < 0.0) var = 0.0;
    float inv = rsqrtf((float)var + BN_EPS);
    long p = (long)s * OC + off + c;
    pool[p] = fmaxf((pool[p] - (float)m) * inv, 0.f);
}

// split w1 [O, 2D] into w1a = w1[:, :D], w1d = w1[:, D:] - w1[:, :D]
__global__ void split_w1_kernel(const float* __restrict__ w1, float* __restrict__ wa,
                                float* __restrict__ wd, int O, int D, int total) {
    int t = blockIdx.x * 256 + threadIdx.x;
    if (t >= total) return;
    int d = t % D, o = t / D;
    float a = w1[(long)o * 2 * D + d];
    float b = w1[(long)o * 2 * D + D + d];
    wa[t] = a;
    wd[t] = b - a;
}

// ----------------------------------------------------------------------------
// Generic fallback GEMM (odd shapes): 64x64 tile
// ----------------------------------------------------------------------------
__global__ void gemm_kernel(const float* __restrict__ A, const float* __restrict__ W,
                            const float* __restrict__ bias, float* __restrict__ C,
                            int R, int D, int O) {
    __shared__ float As[64][17];
    __shared__ float Ws[64][17];
    int tid = threadIdx.x;
    int tr = tid >> 4, tc = tid & 15;
    long rowBase = (long)blockIdx.y * 64;
    int colBase = blockIdx.x * 64;
    float acc[4][4] = {};
    for (int k0 = 0; k0 < D; k0 += 16) {
        #pragma unroll
        for (int e = tid; e < 1024; e += 256) {
            int rr = e >> 4, kk = e & 15;
            long ar = rowBase + rr; int ac = k0 + kk;
            As[rr][kk] = (ar < R && ac < D) ? A[ar * D + ac] : 0.f;
            int wr = colBase + rr;
            Ws[rr][kk] = (wr < O && ac < D) ? W[(long)wr * D + ac] : 0.f;
        }
        __syncthreads();
        #pragma unroll
        for (int kk = 0; kk < 16; kk++) {
            float a[4], w[4];
            #pragma unroll
            for (int i = 0; i < 4; i++) a[i] = As[tr + 16*i][kk];
            #pragma unroll
            for (int j = 0; j < 4; j++) w[j] = Ws[tc + 16*j][kk];
            #pragma unroll
            for (int i = 0; i < 4; i++)
                #pragma unroll
                for (int j = 0; j < 4; j++)
                    acc[i][j] += a[i] * w[j];
        }
        __syncthreads();
    }
    #pragma unroll
    for (int i = 0; i < 4; i++) {
        long row = rowBase + tr + 16*i;
        if (row >= R) continue;
        #pragma unroll
        for (int j = 0; j < 4; j++) {
            int col = colBase + tc + 16*j;
            if (col >= O) continue;
            float vv = acc[i][j];
            if (bias) vv += bias[col];
            C[row * O + col] = vv;
        }
    }
}

// ----------------------------------------------------------------------------
// BN stats / apply
// ----------------------------------------------------------------------------
__global__ void zero_stats_kernel() {
    int t = threadIdx.x;
    g_sum[t] = 0.0; g_sumsq[t] = 0.0;
    g_sum2[t] = 0.0; g_sumsq2[t] = 0.0;
}

__global__ void stats_kernel(const float* __restrict__ X, int R, int C, int rpb) {
    int r0 = blockIdx.x * rpb;
    int r1 = r0 + rpb; if (r1 > R) r1 = R;
    int nch = (C + 255) / 256;
    double acc[4], accsq[4];
    for (int k = 0; k < 4; k++) { acc[k] = 0.0; accsq[k] = 0.0; }
    for (int r = r0; r < r1; r++) {
        const float* row = X + (long)r * C;
        for (int k = 0; k < nch; k++) {
            int c = threadIdx.x + k * 256;
            if (c < C) { double v = row[c]; acc[k] += v; accsq[k] += v * v; }
        }
    }
    for (int k = 0; k < nch; k++) {
        int c = threadIdx.x + k * 256;
        if (c < C) { atomicAdd(&g_sum[c], acc[k]); atomicAdd(&g_sumsq[c], accsq[k]); }
    }
}

__global__ void bn_apply_kernel(float* __restrict__ X, long total, int C, int R, int act) {
    long t = (long)blockIdx.x * blockDim.x + threadIdx.x;
    if (t >= total) return;
    int c = (int)(t % C);
    double m = g_sum[c] / R;
    double var = g_sumsq[c] / R - m * m;
    if (var < 0.0) var = 0.0;
    float inv = rsqrtf((float)var + BN_EPS);
    float y = (X[t] - (float)m) * inv;
    X[t] = (act == 0) ? fmaxf(y, 0.f) : (y >= 0.f ? y : 0.2f * y);
}

__global__ void bn_small_kernel(float* __restrict__ X, int C, float slope) {
    int c = blockIdx.x * blockDim.x + threadIdx.x;
    if (c >= C) return;
    double s = 0.0, ss = 0.0;
    for (int r = 0; r < 8; r++) { double v = X[r * C + c]; s += v; ss += v * v; }
    double m = s / 8.0;
    double var = ss / 8.0 - m * m;
    if (var < 0.0) var = 0.0;
    float inv = rsqrtf((float)var + BN_EPS);
    for (int r = 0; r < 8; r++) {
        float y = (X[r * C + c] - (float)m) * inv;
        X[r * C + c] = y >= 0.f ? y : slope * y;
    }
}

// ----------------------------------------------------------------------------
// Layout / elementwise helpers
// ----------------------------------------------------------------------------
__global__ void transpose_x_kernel(const float* __restrict__ x, float* __restrict__ xyz) {
    int t = blockIdx.x * 256 + threadIdx.x;
    if (t >= 8 * 2048 * 3) return;
    int c = t % 3; int n = (t / 3) % 2048; int b = t / (3 * 2048);
    xyz[t] = x[((long)b * 3 + c) * 2048 + n];
}

__global__ void gather_kernel(const float* __restrict__ src, const int* __restrict__ idx,
                              float* __restrict__ dst, int S, int N, int D, long total) {
    long t = (long)blockIdx.x * blockDim.x + threadIdx.x;
    if (t >= total) return;
    int c = (int)(t % D); long bs = t / D;
    int b = (int)(bs / S);
    dst[t] = src[((long)b * N + idx[bs]) * D + c];
}

__global__ void add_kernel(const float* __restrict__ a, const float* __restrict__ b,
                           float* __restrict__ c, long n) {
    long t = (long)blockIdx.x * blockDim.x + threadIdx.x;
    if (t < n) c[t] = a[t] + b[t];
}

__global__ void sub_kernel(const float* __restrict__ a, const float* __restrict__ b,
                           float* __restrict__ c, long n) {
    long t = (long)blockIdx.x * blockDim.x + threadIdx.x;
    if (t < n) c[t] = a[t] - b[t];
}

__global__ void addcat_kernel(const float* __restrict__ xp, const float* __restrict__ u,
                              float* __restrict__ x, float* __restrict__ cat, int layer) {
    int t = blockIdx.x * 256 + threadIdx.x;
    float v = xp[t] + u[t];
    x[t] = v;
    int c = t & 255; int row = t >> 8;
    cat[(long)row * 1280 + layer * 256 + c] = v;
}

__global__ void catf1_kernel(const float* __restrict__ f1, float* __restrict__ cat) {
    int t = blockIdx.x * 256 + threadIdx.x;
    int c = t & 255; int row = t >> 8;
    cat[(long)row * 1280 + 1024 + c] = f1[t];
}

__global__ void maxn_kernel(const float* __restrict__ X, float* __restrict__ G) {
    int b = blockIdx.x; int c = blockIdx.y * 256 + threadIdx.x;
    float m = -FLT_MAX;
    for (int n = 0; n < 256; n++) m = fmaxf(m, X[((long)b * 256 + n) * 1024 + c]);
    G[b * 1024 + c] = m;
}

// ----------------------------------------------------------------------------
// FPS / kNN (tie semantics match jax)
// ----------------------------------------------------------------------------
__global__ void fps_kernel(const float* __restrict__ xyz, int N, int npoint,
                           int* __restrict__ outIdx) {
    int b = blockIdx.x;
    __shared__ float sx[2048], sy[2048], sz[2048], sd[2048];
    __shared__ float rv[256];
    __shared__ int   ri[256];
    int t = threadIdx.x;
    for (int n = t; n < N; n += 256) {
        sx[n] = xyz[((long)b * N + n) * 3 + 0];
        sy[n] = xyz[((long)b * N + n) * 3 + 1];
        sz[n] = xyz[((long)b * N + n) * 3 + 2];
        sd[n] = 1e10f;
    }
    __syncthreads();
    int far = 0;
    for (int it = 0; it < npoint; it++) {
        if (t == 0) outIdx[b * npoint + it] = far;
        float cx = sx[far], cy = sy[far], cz = sz[far];
        float bestv = -FLT_MAX; int besti = N;
        for (int n = t; n < N; n += 256) {
            float dx = sx[n] - cx, dy = sy[n] - cy, dz = sz[n] - cz;
            float d = dx * dx + dy * dy + dz * dz;
            float dm = fminf(sd[n], d);
            sd[n] = dm;
            if (dm > bestv) { bestv = dm; besti = n; }
        }
        rv[t] = bestv; ri[t] = besti;
        __syncthreads();
        for (int s = 128; s > 0; s >>= 1) {
            if (t < s) {
                float ov = rv[t + s]; int oi = ri[t + s];
                if (ov > rv[t] || (ov == rv[t] && oi < ri[t])) { rv[t] = ov; ri[t] = oi; }
            }
            __syncthreads();
        }
        far = ri[0];
        __syncthreads();
    }
}

__global__ void knn_kernel(const float* __restrict__ centers, const float* __restrict__ xyz,
                           int S, int N, int* __restrict__ knnOut) {
    int bs = blockIdx.x; int b = bs / S;
    __shared__ float sd[2048];
    __shared__ float rv[256];
    __shared__ int   ri[256];
    int t = threadIdx.x;
    float cx = centers[(long)bs * 3 + 0];
    float cy = centers[(long)bs * 3 + 1];
    float cz = centers[(long)bs * 3 + 2];
    float cn = cx * cx + cy * cy + cz * cz;
    for (int n = t; n < N; n += 256) {
        float px = xyz[((long)b * N + n) * 3 + 0];
        float py = xyz[((long)b * N + n) * 3 + 1];
        float pz = xyz[((long)b * N + n) * 3 + 2];
        float pn = px * px + py * py + pz * pz;
        float dot = cx * px + cy * py + cz * pz;
        sd[n] = cn + pn - 2.f * dot;
    }
    __syncthreads();
    for (int j = 0; j < 64; j++) {
        float bestv = FLT_MAX; int besti = N;
        for (int n = t; n < N; n += 256) {
            float v = sd[n];
            if (v < bestv) { bestv = v; besti = n; }
        }
        rv[t] = bestv; ri[t] = besti;
        __syncthreads();
        for (int s = 128; s > 0; s >>= 1) {
            if (t < s) {
                float ov = rv[t + s]; int oi = ri[t + s];
                if (ov < rv[t] || (ov == rv[t] && oi < ri[t])) { rv[t] = ov; ri[t] = oi; }
            }
            __syncthreads();
        }
        int sel = ri[0];
        if (t == 0) { knnOut[(long)bs * 64 + j] = sel; sd[sel] = FLT_MAX; }
        __syncthreads();
    }
}

// ----------------------------------------------------------------------------
// Attention (reference reshape quirk preserved)
// ----------------------------------------------------------------------------
__global__ void gram_kernel(const float* __restrict__ Q, float* __restrict__ A) {
    int bh = blockIdx.z; int b = bh >> 2; int h = bh & 3;
    int i0 = blockIdx.y * 16, j0 = blockIdx.x * 16;
    __shared__ float Qi[16][65];
    __shared__ float Qj[16][65];
    int tid = threadIdx.x;
    for (int e = tid; e < 1024; e += 256) {
        int r = e >> 6, d = e & 63;
        int i = i0 + r;
        Qi[r][d] = Q[((long)b * 256 + h * 64 + (i >> 2)) * 256 + (i & 3) * 64 + d];
        Qj[r][d] = Q[((long)b * 256 + j0 + r) * 256 + h * 64 + d];
    }
    __syncthreads();
    int ti = tid >> 4, tj = tid & 15;
    float acc = 0.f;
    #pragma unroll
    for (int d = 0; d < 64; d++) acc += Qi[ti][d] * Qj[tj][d];
    A[((long)bh * 256 + (i0 + ti)) * 256 + (j0 + tj)] = acc;
}

__global__ void softmax_row_kernel(float* __restrict__ A) {
    __shared__ float red[256];
    long row = blockIdx.x;
    float* p = A + row * 256;
    int t = threadIdx.x;
    float v = p[t];
    red[t] = v; __syncthreads();
    for (int s = 128; s > 0; s >>= 1) { if (t < s) red[t] = fmaxf(red[t], red[t + s]); __syncthreads(); }
    float m = red[0]; __syncthreads();
    float e = expf(v - m);
    red[t] = e; __syncthreads();
    for (int s = 128; s > 0; s >>= 1) { if (t < s) red[t] += red[t + s]; __syncthreads(); }
    p[t] = e / red[0];
}

__global__ void softmax_col_kernel(float* __restrict__ A) {
    __shared__ float red[256];
    int bh = blockIdx.x >> 8; int j = blockIdx.x & 255;
    float* base = A + ((long)bh * 256) * 256 + j;
    int t = threadIdx.x;
    float v = base[(long)t * 256];
    red[t] = v; __syncthreads();
    for (int s = 128; s > 0; s >>= 1) { if (t < s) red[t] = fmaxf(red[t], red[t + s]); __syncthreads(); }
    float m = red[0]; __syncthreads();
    float e = expf(v - m);
    red[t] = e; __syncthreads();
    for (int s = 128; s > 0; s >>= 1) { if (t < s) red[t] += red[t + s]; __syncthreads(); }
    base[(long)t * 256] = e / red[0];
}

__global__ void xr_kernel(const float* __restrict__ V, const float* __restrict__ A2,
                          float* __restrict__ XR) {
    int row = blockIdx.x;
    int b = row >> 8; int i = row & 255;
    int c = threadIdx.x; int h = c >> 6;
    const float* a = A2 + (((long)(b * 4 + h)) * 256) * 256 + i;
    const float* v = V + ((long)b * 256) * 256 + c;
    float acc = 0.f;
    for (int j = 0; j < 256; j++) acc += v[(long)j * 256] * a[(long)j * 256];
    XR[(long)row * 256 + c] = acc;
}

// ----------------------------------------------------------------------------
// Host orchestration
// ----------------------------------------------------------------------------
static void gemm_old(const float* A, const float* W, const float* bias, float* C,
                     int R, int D, int O) {
    dim3 grid(CEILDIV(O, 64), CEILDIV(R, 64));
    gemm_kernel<<<grid, 256>>>(A, W, bias, C, R, D, O);
}

static void gemm_big(const float* A, const float* W, const float* bias, float* C,
                     int R, int D, int O, int useStats, int statN) {
    dim3 grid(CEILDIV(O, 128), R / 128);
    gemm128_kernel<<<grid, 256>>>(A, W, bias, C, R, D, O, useStats, statN);
}

static void computeStats(const float* X, int R, int C) {
    zero_stats_kernel<<<1, 1024>>>();
    int rpb = CEILDIV(R, 1024); if (rpb < 1) rpb = 1;
    int grid = CEILDIV(R, rpb);
    stats_kernel<<<grid, 256>>>(X, R, C, rpb);
}

static void bn(float* X, int R, int C, int act) {
    computeStats(X, R, C);
    long total = (long)R * C;
    bn_apply_kernel<<<(int)CEILDIV(total, 256), 256>>>(X, total, C, R, act);
}

extern "C" void kernel_launch(void* const* d_in, const int* in_sizes, int n_in,
                              void* d_out, int out_size) {
    const float* x       = (const float*)d_in[0];
    const float* conv1_w = (const float*)d_in[1];
    const float* conv2_w = (const float*)d_in[2];
    const float* g0_w1   = (const float*)d_in[3];
    const float* g0_w2   = (const float*)d_in[4];
    const float* g0_wc   = (const float*)d_in[5];
    const float* g1_w1   = (const float*)d_in[6];
    const float* g1_w2   = (const float*)d_in[7];
    const float* g1_wc   = (const float*)d_in[8];
    const float* pt_w    = (const float*)d_in[9];
    const float* pos_w   = (const float*)d_in[10];
    const float* pos_b   = (const float*)d_in[11];
    const float* sa_wqk  = (const float*)d_in[12];
    const float* sa_wv   = (const float*)d_in[13];
    const float* sa_bv   = (const float*)d_in[14];
    const float* sa_wt   = (const float*)d_in[15];
    const float* sa_bt   = (const float*)d_in[16];
    const float* fuse_w  = (const float*)d_in[17];
    const float* lin1_w  = (const float*)d_in[18];
    const float* lin2_w  = (const float*)d_in[19];
    const float* lin2_b  = (const float*)d_in[20];
    const float* lin3_w  = (const float*)d_in[21];
    const float* lin3_b  = (const float*)d_in[22];
    float* out = (float*)d_out;

    float *xyz, *h1, *points, *newxyz, *newxyz2, *newpts, *Ub, *Vb, *w1a, *w1d, *pool, *f0, *f1;
    float *pos, *xx, *xp, *qb, *vb, *xrb, *attn, *catb, *fuseb, *gmax, *l1, *l2;
    int *fpsidx, *knn;
    cudaGetSymbolAddress((void**)&xyz, g_xyz);
    cudaGetSymbolAddress((void**)&h1, g_h1);
    cudaGetSymbolAddress((void**)&points, g_points);
    cudaGetSymbolAddress((void**)&fpsidx, g_fpsidx);
    cudaGetSymbolAddress((void**)&newxyz, g_newxyz);
    cudaGetSymbolAddress((void**)&newxyz2, g_newxyz2);
    cudaGetSymbolAddress((void**)&newpts, g_newpts);
    cudaGetSymbolAddress((void**)&knn, g_knn);
    cudaGetSymbolAddress((void**)&Ub, g_U);
    cudaGetSymbolAddress((void**)&Vb, g_V);
    cudaGetSymbolAddress((void**)&w1a, g_w1a);
    cudaGetSymbolAddress((void**)&w1d, g_w1d);
    cudaGetSymbolAddress((void**)&pool, g_pool);
    cudaGetSymbolAddress((void**)&f0, g_f0);
    cudaGetSymbolAddress((void**)&f1, g_f1);
    cudaGetSymbolAddress((void**)&pos, g_pos);
    cudaGetSymbolAddress((void**)&xx, g_x);
    cudaGetSymbolAddress((void**)&xp, g_xp);
    cudaGetSymbolAddress((void**)&qb, g_q);
    cudaGetSymbolAddress((void**)&vb, g_v);
    cudaGetSymbolAddress((void**)&xrb, g_xr);
    cudaGetSymbolAddress((void**)&attn, g_attn);
    cudaGetSymbolAddress((void**)&catb, g_cat);
    cudaGetSymbolAddress((void**)&fuseb, g_fuse);
    cudaGetSymbolAddress((void**)&gmax, g_gmax);
    cudaGetSymbolAddress((void**)&l1, g_l1);
    cudaGetSymbolAddress((void**)&l2, g_l2);

    // ---- Stage A: input transpose + conv1/conv2 (+BN,ReLU) ----
    transpose_x_kernel<<<CEILDIV(8*2048*3, 256), 256>>>(x, xyz);
    gemm_old(xyz, conv1_w, nullptr, h1, 16384, 3, 64);
    computeStats(h1, 16384, 64);
    gemm_big(h1, conv2_w, nullptr, points, 16384, 64, 64, 1, 16384);
    bn(points, 16384, 64, 0);

    // ---- Stage B: FPS(512) + gather + kNN(64) over 2048 pts ----
    fps_kernel<<<8, 256>>>(xyz, 2048, 512, fpsidx);
    gather_kernel<<<CEILDIV(8*512*3, 256), 256>>>(xyz, fpsidx, newxyz, 512, 2048, 3, 8L*512*3);
    gather_kernel<<<CEILDIV(8*512*64, 256), 256>>>(points, fpsidx, newpts, 512, 2048, 64, 8L*512*64);
    knn_kernel<<<8*512, 256>>>(newxyz, xyz, 512, 2048, knn);

    // ---- Stage C: local_op 0 via U/V decomposition ----
    {
        split_w1_kernel<<<CEILDIV(128*64, 256), 256>>>(g0_w1, w1a, w1d, 128, 64, 128*64);
        gemm_big(points, w1a, nullptr, Ub, 16384, 64, 128, 0, 0);   // U: 16384x128
        gemm_big(newpts, w1d, nullptr, Vb, 4096, 64, 128, 0, 0);    // V: 4096x128
        const int ks[3] = {16, 32, 64};
        const int kshift[3] = {4, 5, 6};
        for (int si = 0; si < 3; si++) {
            int k = ks[si];
            int R = 8 * 512 * k;
            zero_stats_kernel<<<1, 1024>>>();
            stats1_kernel<<<4096, 128>>>(Ub, Vb, knn, 512, 2048, 128, k);
            dim3 grid(1, R / 128);
            local_gemm2_kernel<<<grid, 256>>>(Ub, Vb, knn, g0_w2, pool,
                                              512, 2048, 128, 128, kshift[si], R, 384, si * 128);
            pool_finalize_kernel<<<4096, 128>>>(pool, 384, si * 128, R);
        }
        gemm_big(pool, g0_wc, nullptr, f0, 4096, 384, 128, 0, 0);
        bn(f0, 4096, 128, 0);
    }

    // ---- Stage D: FPS(256) + gather + kNN over 512 centers ----
    fps_kernel<<<8, 256>>>(newxyz, 512, 256, fpsidx);
    gather_kernel<<<CEILDIV(8*256*3, 256), 256>>>(newxyz, fpsidx, newxyz2, 256, 512, 3, 8L*256*3);
    gather_kernel<<<CEILDIV(8*256*128, 256), 256>>>(f0, fpsidx, newpts, 256, 512, 128, 8L*256*128);
    knn_kernel<<<8*256, 256>>>(newxyz2, newxyz, 256, 512, knn);

    // ---- Stage E: local_op 1 via U/V decomposition ----
    {
        split_w1_kernel<<<CEILDIV(256*128, 256), 256>>>(g1_w1, w1a, w1d, 256, 128, 256*128);
        gemm_big(f0, w1a, nullptr, Ub, 4096, 128, 256, 0, 0);       // U2: 4096x256
        gemm_big(newpts, w1d, nullptr, Vb, 2048, 128, 256, 0, 0);   // V2: 2048x256
        const int ks[3] = {16, 32, 64};
        const int kshift[3] = {4, 5, 6};
        for (int si = 0; si < 3; si++) {
            int k = ks[si];
            int R = 8 * 256 * k;
            zero_stats_kernel<<<1, 1024>>>();
            stats1_kernel<<<2048, 256>>>(Ub, Vb, knn, 256, 512, 256, k);
            dim3 grid(2, R / 128);
            local_gemm2_kernel<<<grid, 256>>>(Ub, Vb, knn, g1_w2, pool,
                                              256, 512, 256, 256, kshift[si], R, 768, si * 256);
            pool_finalize_kernel<<<2048, 256>>>(pool, 768, si * 256, R);
        }
        gemm_big(pool, g1_wc, nullptr, f1, 2048, 768, 256, 0, 0);
        bn(f1, 2048, 256, 0);
    }

    // ---- Stage F: pos embedding + pt conv ----
    gemm_old(newxyz2, pos_w, pos_b, pos, 2048, 3, 256);
    gemm_big(f1, pt_w, nullptr, xx, 2048, 256, 256, 0, 0);
    bn(xx, 2048, 256, 0);

    // ---- Stage G: 4 offset self-attention layers ----
    for (int i = 0; i < 4; i++) {
        add_kernel<<<2048, 256>>>(xx, pos, xp, 8L*256*256);
        gemm_big(xp, sa_wqk + (long)i * 256 * 256, nullptr, qb, 2048, 256, 256, 0, 0);
        gemm_big(xp, sa_wv + (long)i * 256 * 256, sa_bv + i * 256, vb, 2048, 256, 256, 0, 0);
        gram_kernel<<<dim3(16, 16, 32), 256>>>(qb, attn);
        softmax_row_kernel<<<8192, 256>>>(attn);
        softmax_col_kernel<<<8192, 256>>>(attn);
        xr_kernel<<<2048, 256>>>(vb, attn, xrb);
        sub_kernel<<<2048, 256>>>(xp, xrb, xrb, 8L*256*256);
        gemm_big(xrb, sa_wt + (long)i * 256 * 256, sa_bt + i * 256, qb, 2048, 256, 256, 0, 0);
        bn(qb, 2048, 256, 0);
        addcat_kernel<<<2048, 256>>>(xp, qb, xx, catb, i);
    }
    catf1_kernel<<<2048, 256>>>(f1, catb);

    // ---- Stage H: fuse conv + global max + MLP head ----
    gemm_big(catb, fuse_w, nullptr, fuseb, 2048, 1280, 1024, 0, 0);
    bn(fuseb, 2048, 1024, 1);
    maxn_kernel<<<dim3(8, 4), 256>>>(fuseb, gmax);
    gemm_old(gmax, lin1_w, nullptr, l1, 8, 1024, 512);
    bn_small_kernel<<<2, 256>>>(l1, 512, 0.2f);
    gemm_old(l1, lin2_w, lin2_b, l2, 8, 512, 256);
    bn_small_kernel<<<1, 256>>>(l2, 256, 0.2f);
    gemm_old(l2, lin3_w, lin3_b, out, 8, 256, 40);
}

// round 5
// speedup vs baseline: 2.1808x; 1.1889x over previous
#include <cuda_runtime.h>
#include <math.h>
#include <float.h>

#define CEILDIV(a,b) (((a)+(b)-1)/(b))
#define BN_EPS 1e-5f
#define PART_OFF (2048*256)

// ----------------------------------------------------------------------------
// Scratch (device globals)
// ----------------------------------------------------------------------------
__device__ float g_xyz[8*2048*3];
__device__ float g_h1[8*2048*64];
__device__ float g_points[8*2048*64];
__device__ int   g_fpsidx[8*512];
__device__ float g_newxyz[8*512*3];
__device__ float g_newxyz2[8*256*3];
__device__ float g_newpts[8*512*64];        // stage2: 8*256*128
__device__ int   g_knn[8*512*64];           // stage-1 kNN lists
__device__ int   g_knn2[8*256*64];          // stage-2 kNN lists (separate! R4 bug was aliasing)
__device__ float g_U[16384*128];            // stage E: 4096x256
__device__ float g_V[4096*128];             // stage E: 2048x256
__device__ float g_w1a[256*128];
__device__ float g_w1d[256*128];
__device__ float g_part[2*2048*256];        // per-block partial sums / sumsq
__device__ float g_pool[8*512*384];         // stage2: 8*256*768
__device__ float g_f0[8*512*128];
__device__ float g_f1[8*256*256];
__device__ float g_pos[8*256*256];
__device__ float g_x[8*256*256];
__device__ float g_q[8*256*256];
__device__ float g_v[8*256*256];
__device__ float g_xr[8*256*256];
__device__ float g_attn[8*4*256*256];
__device__ float g_cat[8*256*1280];
__device__ float g_fuse[8*256*1024];
__device__ float g_gmax[8*1024];
__device__ float g_l1[8*512];
__device__ float g_l2[8*256];
__device__ double g_sum[1024];
__device__ double g_sumsq[1024];
__device__ float g_m1[1024];
__device__ float g_i1[1024];
__device__ float g_m2[256];
__device__ float g_i2[256];

// ----------------------------------------------------------------------------
// BN stats plumbing
// ----------------------------------------------------------------------------
__global__ void zero_stats_kernel() {
    int t = threadIdx.x;
    g_sum[t] = 0.0; g_sumsq[t] = 0.0;
}

__global__ void stats_kernel(const float* __restrict__ X, int R, int C, int rpb) {
    int r0 = blockIdx.x * rpb;
    int r1 = r0 + rpb; if (r1 > R) r1 = R;
    int nch = (C + 255) / 256;
    double acc[4], accsq[4];
    for (int k = 0; k < 4; k++) { acc[k] = 0.0; accsq[k] = 0.0; }
    for (int r = r0; r < r1; r++) {
        const float* row = X + (long)r * C;
        for (int k = 0; k < nch; k++) {
            int c = threadIdx.x + k * 256;
            if (c < C) { double v = row[c]; acc[k] += v; accsq[k] += v * v; }
        }
    }
    for (int k = 0; k < nch; k++) {
        int c = threadIdx.x + k * 256;
        if (c < C) { atomicAdd(&g_sum[c], acc[k]); atomicAdd(&g_sumsq[c], accsq[k]); }
    }
}

__global__ void finalize1_kernel(int C, int statN) {
    int c = blockIdx.x * 256 + threadIdx.x;
    if (c >= C) return;
    double m = g_sum[c] / statN;
    double var = g_sumsq[c] / statN - m * m;
    if (var < 0.0) var = 0.0;
    g_m1[c] = (float)m;
    g_i1[c] = rsqrtf((float)var + BN_EPS);
}

// act: 0 = relu, 1 = leaky(0.2)
__global__ void bn_apply_kernel(float* __restrict__ X, long total, int C, int act) {
    long t = (long)blockIdx.x * blockDim.x + threadIdx.x;
    if (t >= total) return;
    int c = (int)(t % C);
    float y = (X[t] - g_m1[c]) * g_i1[c];
    X[t] = (act == 0) ? fmaxf(y, 0.f) : (y >= 0.f ? y : 0.2f * y);
}

__global__ void bn_small_kernel(float* __restrict__ X, int C, float slope) {
    int c = blockIdx.x * blockDim.x + threadIdx.x;
    if (c >= C) return;
    double s = 0.0, ss = 0.0;
    for (int r = 0; r < 8; r++) { double v = X[r * C + c]; s += v; ss += v * v; }
    double m = s / 8.0;
    double var = ss / 8.0 - m * m;
    if (var < 0.0) var = 0.0;
    float inv = rsqrtf((float)var + BN_EPS);
    for (int r = 0; r < 8; r++) {
        float y = (X[r * C + c] - (float)m) * inv;
        X[r * C + c] = y >= 0.f ? y : slope * y;
    }
}

// reduce per-block partials -> g_m2/g_i2 (for BN2 of local op)
__global__ void reduce_part_kernel(int nBy, int O, int statN) {
    int c = blockIdx.x;
    int t = threadIdx.x;
    double a = 0.0, b = 0.0;
    for (int r = t; r < nBy; r += 256) {
        a += g_part[r * O + c];
        b += g_part[PART_OFF + r * O + c];
    }
    __shared__ double sa[256], sb[256];
    sa[t] = a; sb[t] = b;
    __syncthreads();
    for (int s = 128; s > 0; s >>= 1) {
        if (t < s) { sa[t] += sa[t + s]; sb[t] += sb[t + s]; }
        __syncthreads();
    }
    if (t == 0) {
        double m = sa[0] / statN;
        double var = sb[0] / statN - m * m;
        if (var < 0.0) var = 0.0;
        g_m2[c] = (float)m;
        g_i2[c] = rsqrtf((float)var + BN_EPS);
    }
}

// ----------------------------------------------------------------------------
// 128x128 tiled GEMM (optionally BN+relu on A via g_m1/g_i1)
// ----------------------------------------------------------------------------
__global__ void gemm128_kernel(const float* __restrict__ A, const float* __restrict__ W,
                               const float* __restrict__ bias, float* __restrict__ C,
                               int R, int D, int O, int useStats) {
    __shared__ float As[16][132];
    __shared__ float Ws[16][132];
    __shared__ float sM[256];
    __shared__ float sI[256];
    int tid = threadIdx.x;
    if (useStats) {
        for (int c = tid; c < D; c += 256) { sM[c] = g_m1[c]; sI[c] = g_i1[c]; }
        __syncthreads();
    }
    long rowBase = (long)blockIdx.y * 128;
    int colBase = blockIdx.x * 128;
    int tr = tid >> 4, tc = tid & 15;
    int lrow = tid >> 2;
    int lkq = tid & 3;
    float acc[8][8];
    #pragma unroll
    for (int i = 0; i < 8; i++)
        #pragma unroll
        for (int j = 0; j < 8; j++) acc[i][j] = 0.f;

    for (int k0 = 0; k0 < D; k0 += 16) {
        #pragma unroll
        for (int half = 0; half < 2; half++) {
            int row = lrow + 64 * half;
            int kc = k0 + lkq * 4;
            float4 av = *(const float4*)(A + (rowBase + row) * D + kc);
            if (useStats) {
                av.x = fmaxf((av.x - sM[kc + 0]) * sI[kc + 0], 0.f);
                av.y = fmaxf((av.y - sM[kc + 1]) * sI[kc + 1], 0.f);
                av.z = fmaxf((av.z - sM[kc + 2]) * sI[kc + 2], 0.f);
                av.w = fmaxf((av.w - sM[kc + 3]) * sI[kc + 3], 0.f);
            }
            As[lkq * 4 + 0][row] = av.x;
            As[lkq * 4 + 1][row] = av.y;
            As[lkq * 4 + 2][row] = av.z;
            As[lkq * 4 + 3][row] = av.w;
            int wr = colBase + row;
            float4 wv = make_float4(0.f, 0.f, 0.f, 0.f);
            if (wr < O) wv = *(const float4*)(W + (long)wr * D + kc);
            Ws[lkq * 4 + 0][row] = wv.x;
            Ws[lkq * 4 + 1][row] = wv.y;
            Ws[lkq * 4 + 2][row] = wv.z;
            Ws[lkq * 4 + 3][row] = wv.w;
        }
        __syncthreads();
        #pragma unroll
        for (int kk = 0; kk < 16; kk++) {
            float a[8], w[8];
            *(float4*)(a + 0) = *(const float4*)&As[kk][tr * 8 + 0];
            *(float4*)(a + 4) = *(const float4*)&As[kk][tr * 8 + 4];
            *(float4*)(w + 0) = *(const float4*)&Ws[kk][tc * 8 + 0];
            *(float4*)(w + 4) = *(const float4*)&Ws[kk][tc * 8 + 4];
            #pragma unroll
            for (int i = 0; i < 8; i++)
                #pragma unroll
                for (int j = 0; j < 8; j++)
                    acc[i][j] += a[i] * w[j];
        }
        __syncthreads();
    }
    #pragma unroll
    for (int i = 0; i < 8; i++) {
        long row = rowBase + tr * 8 + i;
        int col0 = colBase + tc * 8;
        if (col0 >= O) continue;
        float b0 = 0, b1 = 0, b2 = 0, b3 = 0, b4 = 0, b5 = 0, b6 = 0, b7 = 0;
        if (bias) {
            b0 = bias[col0 + 0]; b1 = bias[col0 + 1]; b2 = bias[col0 + 2]; b3 = bias[col0 + 3];
            b4 = bias[col0 + 4]; b5 = bias[col0 + 5]; b6 = bias[col0 + 6]; b7 = bias[col0 + 7];
        }
        float4 v0 = make_float4(acc[i][0] + b0, acc[i][1] + b1, acc[i][2] + b2, acc[i][3] + b3);
        float4 v1 = make_float4(acc[i][4] + b4, acc[i][5] + b5, acc[i][6] + b6, acc[i][7] + b7);
        *(float4*)(C + row * O + col0) = v0;
        *(float4*)(C + row * O + col0 + 4) = v1;
    }
}

// ----------------------------------------------------------------------------
// Fused local-op GEMM2 (A built on the fly, BN1 from g_m1/g_i1; epilogue:
// per-center raw max -> pool, per-block channel partials -> g_part)
// ----------------------------------------------------------------------------
__global__ void local_gemm2_kernel(const float* __restrict__ U, const float* __restrict__ V,
                                   const int* __restrict__ knn, const float* __restrict__ W,
                                   float* __restrict__ poolOut,
                                   int S, int N, int D, int O, int kshift,
                                   int OC, int off) {
    __shared__ float As[16][132];
    __shared__ float Ws[16][132];
    __shared__ float sRed[16][132];
    __shared__ float sM[256];
    __shared__ float sI[256];
    __shared__ int sP[128];
    __shared__ int sS[128];
    int tid = threadIdx.x;
    long rowBase = (long)blockIdx.y * 128;
    int colBase = blockIdx.x * 128;

    for (int c = tid; c < D; c += 256) { sM[c] = g_m1[c]; sI[c] = g_i1[c]; }
    if (tid < 128) {
        long grow = rowBase + tid;
        int s = (int)(grow >> kshift);
        int j = (int)(grow & ((1 << kshift) - 1));
        int b = s / S;
        sS[tid] = s;
        sP[tid] = b * N + knn[(long)s * 64 + j];
    }
    __syncthreads();

    int tr = tid >> 4, tc = tid & 15;
    int lrow = tid >> 2;
    int lkq = tid & 3;
    float acc[8][8];
    #pragma unroll
    for (int i = 0; i < 8; i++)
        #pragma unroll
        for (int j = 0; j < 8; j++) acc[i][j] = 0.f;

    for (int k0 = 0; k0 < D; k0 += 16) {
        #pragma unroll
        for (int half = 0; half < 2; half++) {
            int row = lrow + 64 * half;
            int kc = k0 + lkq * 4;
            float4 uv = *(const float4*)(U + (long)sP[row] * D + kc);
            float4 vv = *(const float4*)(V + (long)sS[row] * D + kc);
            As[lkq * 4 + 0][row] = fmaxf((uv.x + vv.x - sM[kc + 0]) * sI[kc + 0], 0.f);
            As[lkq * 4 + 1][row] = fmaxf((uv.y + vv.y - sM[kc + 1]) * sI[kc + 1], 0.f);
            As[lkq * 4 + 2][row] = fmaxf((uv.z + vv.z - sM[kc + 2]) * sI[kc + 2], 0.f);
            As[lkq * 4 + 3][row] = fmaxf((uv.w + vv.w - sM[kc + 3]) * sI[kc + 3], 0.f);
            float4 wv = *(const float4*)(W + (long)(colBase + row) * D + kc);
            Ws[lkq * 4 + 0][row] = wv.x;
            Ws[lkq * 4 + 1][row] = wv.y;
            Ws[lkq * 4 + 2][row] = wv.z;
            Ws[lkq * 4 + 3][row] = wv.w;
        }
        __syncthreads();
        #pragma unroll
        for (int kk = 0; kk < 16; kk++) {
            float a[8], w[8];
            *(float4*)(a + 0) = *(const float4*)&As[kk][tr * 8 + 0];
            *(float4*)(a + 4) = *(const float4*)&As[kk][tr * 8 + 4];
            *(float4*)(w + 0) = *(const float4*)&Ws[kk][tc * 8 + 0];
            *(float4*)(w + 4) = *(const float4*)&Ws[kk][tc * 8 + 4];
            #pragma unroll
            for (int i = 0; i < 8; i++)
                #pragma unroll
                for (int j = 0; j < 8; j++)
                    acc[i][j] += a[i] * w[j];
        }
        __syncthreads();
    }

    // epilogue 1: per-center raw max -> poolOut
    int g = (1 << kshift) >> 3;
    #pragma unroll
    for (int j = 0; j < 8; j++) {
        float m = acc[0][j];
        #pragma unroll
        for (int i = 1; i < 8; i++) m = fmaxf(m, acc[i][j]);
        sRed[tr][tc * 8 + j] = m;
    }
    __syncthreads();
    if ((tr & (g - 1)) == 0) {
        int s = sS[tr * 8];
        #pragma unroll
        for (int j = 0; j < 8; j++) {
            float m = sRed[tr][tc * 8 + j];
            for (int q = 1; q < g; q++) m = fmaxf(m, sRed[tr + q][tc * 8 + j]);
            poolOut[(long)s * OC + off + colBase + tc * 8 + j] = m;
        }
    }
    __syncthreads();
    // epilogue 2: per-block channel sums -> g_part
    #pragma unroll
    for (int j = 0; j < 8; j++) {
        float sm = 0.f;
        #pragma unroll
        for (int i = 0; i < 8; i++) sm += acc[i][j];
        sRed[tr][tc * 8 + j] = sm;
    }
    __syncthreads();
    if (tr == 0) {
        #pragma unroll
        for (int j = 0; j < 8; j++) {
            float tot = 0.f;
            for (int q = 0; q < 16; q++) tot += sRed[q][tc * 8 + j];
            g_part[(long)blockIdx.y * O + colBase + tc * 8 + j] = tot;
        }
    }
    __syncthreads();
    #pragma unroll
    for (int j = 0; j < 8; j++) {
        float sm = 0.f;
        #pragma unroll
        for (int i = 0; i < 8; i++) sm += acc[i][j] * acc[i][j];
        sRed[tr][tc * 8 + j] = sm;
    }
    __syncthreads();
    if (tr == 0) {
        #pragma unroll
        for (int j = 0; j < 8; j++) {
            float tot = 0.f;
            for (int q = 0; q < 16; q++) tot += sRed[q][tc * 8 + j];
            g_part[PART_OFF + (long)blockIdx.y * O + colBase + tc * 8 + j] = tot;
        }
    }
}

// BN1 stats over layer-1 values (U[idx]+V); cpb centers per block, C threads.
__global__ void stats1_kernel(const float* __restrict__ U, const float* __restrict__ V,
                              const int* __restrict__ knn, int S, int N, int C, int k, int cpb) {
    int c = threadIdx.x;
    int s0 = blockIdx.x * cpb;
    double acc = 0.0, accsq = 0.0;
    for (int ss = 0; ss < cpb; ss++) {
        int s = s0 + ss;
        int b = s / S;
        float v = V[(long)s * C + c];
        const int* kn = knn + (long)s * 64;
        for (int j = 0; j < k; j++) {
            float u = U[((long)b * N + kn[j]) * C + c];
            float x = u + v;
            acc += x;
            accsq += x * x;
        }
    }
    atomicAdd(&g_sum[c], acc);
    atomicAdd(&g_sumsq[c], accsq);
}

// pool[s, off+c] = relu(bn2(rawmax)) via g_m2/g_i2
__global__ void pool_finalize_kernel(float* __restrict__ pool, int OC, int off) {
    int s = blockIdx.x;
    int c = threadIdx.x;
    long p = (long)s * OC + off + c;
    pool[p] = fmaxf((pool[p] - g_m2[c]) * g_i2[c], 0.f);
}

__global__ void split_w1_kernel(const float* __restrict__ w1, float* __restrict__ wa,
                                float* __restrict__ wd, int O, int D, int total) {
    int t = blockIdx.x * 256 + threadIdx.x;
    if (t >= total) return;
    int d = t % D, o = t / D;
    float a = w1[(long)o * 2 * D + d];
    float b = w1[(long)o * 2 * D + D + d];
    wa[t] = a;
    wd[t] = b - a;
}

// ----------------------------------------------------------------------------
// Generic fallback GEMM (odd shapes)
// ----------------------------------------------------------------------------
__global__ void gemm_kernel(const float* __restrict__ A, const float* __restrict__ W,
                            const float* __restrict__ bias, float* __restrict__ C,
                            int R, int D, int O) {
    __shared__ float As[64][17];
    __shared__ float Ws[64][17];
    int tid = threadIdx.x;
    int tr = tid >> 4, tc = tid & 15;
    long rowBase = (long)blockIdx.y * 64;
    int colBase = blockIdx.x * 64;
    float acc[4][4] = {};
    for (int k0 = 0; k0 < D; k0 += 16) {
        #pragma unroll
        for (int e = tid; e < 1024; e += 256) {
            int rr = e >> 4, kk = e & 15;
            long ar = rowBase + rr; int ac = k0 + kk;
            As[rr][kk] = (ar < R && ac < D) ? A[ar * D + ac] : 0.f;
            int wr = colBase + rr;
            Ws[rr][kk] = (wr < O && ac < D) ? W[(long)wr * D + ac] : 0.f;
        }
        __syncthreads();
        #pragma unroll
        for (int kk = 0; kk < 16; kk++) {
            float a[4], w[4];
            #pragma unroll
            for (int i = 0; i < 4; i++) a[i] = As[tr + 16*i][kk];
            #pragma unroll
            for (int j = 0; j < 4; j++) w[j] = Ws[tc + 16*j][kk];
            #pragma unroll
            for (int i = 0; i < 4; i++)
                #pragma unroll
                for (int j = 0; j < 4; j++)
                    acc[i][j] += a[i] * w[j];
        }
        __syncthreads();
    }
    #pragma unroll
    for (int i = 0; i < 4; i++) {
        long row = rowBase + tr + 16*i;
        if (row >= R) continue;
        #pragma unroll
        for (int j = 0; j < 4; j++) {
            int col = colBase + tc + 16*j;
            if (col >= O) continue;
            float vv = acc[i][j];
            if (bias) vv += bias[col];
            C[row * O + col] = vv;
        }
    }
}

// ----------------------------------------------------------------------------
// Layout / elementwise helpers
// ----------------------------------------------------------------------------
__global__ void transpose_x_kernel(const float* __restrict__ x, float* __restrict__ xyz) {
    int t = blockIdx.x * 256 + threadIdx.x;
    if (t >= 8 * 2048 * 3) return;
    int c = t % 3; int n = (t / 3) % 2048; int b = t / (3 * 2048);
    xyz[t] = x[((long)b * 3 + c) * 2048 + n];
}

__global__ void gather_kernel(const float* __restrict__ src, const int* __restrict__ idx,
                              float* __restrict__ dst, int S, int N, int D, long total) {
    long t = (long)blockIdx.x * blockDim.x + threadIdx.x;
    if (t >= total) return;
    int c = (int)(t % D); long bs = t / D;
    int b = (int)(bs / S);
    dst[t] = src[((long)b * N + idx[bs]) * D + c];
}

__global__ void catf1_kernel(const float* __restrict__ f1, float* __restrict__ cat) {
    int t = blockIdx.x * 256 + threadIdx.x;
    int c = t & 255; int row = t >> 8;
    cat[(long)row * 1280 + 1024 + c] = f1[t];
}

__global__ void maxn_kernel(const float* __restrict__ X, float* __restrict__ G) {
    int b = blockIdx.x; int c = blockIdx.y * 256 + threadIdx.x;
    float m = -FLT_MAX;
    for (int n = 0; n < 256; n++) m = fmaxf(m, X[((long)b * 256 + n) * 1024 + c]);
    G[b * 1024 + c] = m;
}

// ----------------------------------------------------------------------------
// FPS / kNN with warp-shuffle reductions (tie order preserved)
// ----------------------------------------------------------------------------
__device__ __forceinline__ unsigned keymap(float f) {
    unsigned u = __float_as_uint(f);
    return (u & 0x80000000u) ? ~u : (u | 0x80000000u);
}

__device__ void fps_body(const float* __restrict__ xyz, int N, int npoint,
                         int* __restrict__ outIdx, int b,
                         float* sx, float* sy, float* sz, float* sd,
                         unsigned long long* warpBest, int* sFar) {
    int t = threadIdx.x;
    int nt = blockDim.x;
    int numWarps = nt >> 5;
    for (int n = t; n < N; n += nt) {
        sx[n] = xyz[((long)b * N + n) * 3 + 0];
        sy[n] = xyz[((long)b * N + n) * 3 + 1];
        sz[n] = xyz[((long)b * N + n) * 3 + 2];
        sd[n] = 1e10f;
    }
    __syncthreads();
    int far = 0;
    for (int it = 0; it < npoint; it++) {
        if (t == 0) outIdx[b * npoint + it] = far;
        float cx = sx[far], cy = sy[far], cz = sz[far];
        unsigned long long best = 0ull;
        for (int n = t; n < N; n += nt) {
            float dx = sx[n] - cx, dy = sy[n] - cy, dz = sz[n] - cz;
            float d = dx * dx + dy * dy + dz * dz;
            float dm = fminf(sd[n], d);
            sd[n] = dm;
            unsigned long long key = ((unsigned long long)keymap(dm) << 32) | (unsigned)(~n);
            if (key > best) best = key;
        }
        #pragma unroll
        for (int o = 16; o > 0; o >>= 1) {
            unsigned long long other = __shfl_xor_sync(0xffffffffu, best, o);
            if (other > best) best = other;
        }
        if ((t & 31) == 0) warpBest[t >> 5] = best;
        __syncthreads();
        if (t < 32) {
            unsigned long long v = (t < numWarps) ? warpBest[t] : 0ull;
            #pragma unroll
            for (int o = 16; o > 0; o >>= 1) {
                unsigned long long other = __shfl_xor_sync(0xffffffffu, v, o);
                if (other > v) v = other;
            }
            if (t == 0) *sFar = (int)(~((unsigned)(v & 0xffffffffu)));
        }
        __syncthreads();
        far = *sFar;
    }
}

__device__ void knn_body(const float* __restrict__ centers, const float* __restrict__ xyz,
                         int S, int N, int* __restrict__ knnOut, int bs,
                         float* sd, unsigned long long* warpBest) {
    int t = threadIdx.x;
    int nt = blockDim.x;
    int numWarps = nt >> 5;
    int b = bs / S;
    float cx = centers[(long)bs * 3 + 0];
    float cy = centers[(long)bs * 3 + 1];
    float cz = centers[(long)bs * 3 + 2];
    float cn = cx * cx + cy * cy + cz * cz;
    for (int n = t; n < N; n += nt) {
        float px = xyz[((long)b * N + n) * 3 + 0];
        float py = xyz[((long)b * N + n) * 3 + 1];
        float pz = xyz[((long)b * N + n) * 3 + 2];
        float pn = px * px + py * py + pz * pz;
        float dot = cx * px + cy * py + cz * pz;
        sd[n] = cn + pn - 2.f * dot;
    }
    __syncthreads();
    for (int j = 0; j < 64; j++) {
        unsigned long long best = 0xFFFFFFFFFFFFFFFFull;
        for (int n = t; n < N; n += nt) {
            unsigned long long key = ((unsigned long long)keymap(sd[n]) << 32) | (unsigned)n;
            if (key < best) best = key;
        }
        #pragma unroll
        for (int o = 16; o > 0; o >>= 1) {
            unsigned long long other = __shfl_xor_sync(0xffffffffu, best, o);
            if (other < best) best = other;
        }
        if ((t & 31) == 0) warpBest[t >> 5] = best;
        __syncthreads();
        if (t < 32) {
            unsigned long long v = (t < numWarps) ? warpBest[t] : 0xFFFFFFFFFFFFFFFFull;
            #pragma unroll
            for (int o = 16; o > 0; o >>= 1) {
                unsigned long long other = __shfl_xor_sync(0xffffffffu, v, o);
                if (other < v) v = other;
            }
            if (t == 0) {
                int sel = (int)(v & 0xffffffffu);
                knnOut[(long)bs * 64 + j] = sel;
                sd[sel] = FLT_MAX;
            }
        }
        __syncthreads();
    }
}

__global__ void fps_kernel(const float* xyz, int N, int npoint, int* outIdx) {
    __shared__ float buf[4 * 2048];
    __shared__ unsigned long long wb[32];
    __shared__ int sFar;
    fps_body(xyz, N, npoint, outIdx, blockIdx.x, buf, buf + N, buf + 2 * N, buf + 3 * N, wb, &sFar);
}

__global__ void knn_kernel(const float* centers, const float* xyz, int S, int N, int* knnOut) {
    __shared__ float buf[2048];
    __shared__ unsigned long long wb[32];
    knn_body(centers, xyz, S, N, knnOut, blockIdx.x, buf, wb);
}

// knn over stage-1 centers co-launched with stage-2 FPS (independent work)
__global__ void knn_fps_kernel(const float* centers, const float* xyz, int S, int N,
                               int* knnOut, int nKnn,
                               const float* xyz2, int N2, int np2, int* outIdx2) {
    __shared__ float buf[4 * 2048];
    __shared__ unsigned long long wb[32];
    __shared__ int sFar;
    if (blockIdx.x < nKnn) {
        knn_body(centers, xyz, S, N, knnOut, blockIdx.x, buf, wb);
    } else {
        int b = blockIdx.x - nKnn;
        fps_body(xyz2, N2, np2, outIdx2, b, buf, buf + N2, buf + 2 * N2, buf + 3 * N2, wb, &sFar);
    }
}

// ----------------------------------------------------------------------------
// Attention (reference reshape quirk preserved)
// ----------------------------------------------------------------------------
// dual-output GEMM: A = xx + pos (on the fly); cols [0,256) -> qb (wqk),
// cols [256,512) -> vb (wv + bv). D = 256. grid (4, 16).
__global__ void gemmqv_kernel(const float* __restrict__ xx, const float* __restrict__ pos,
                              const float* __restrict__ wqk, const float* __restrict__ wv,
                              const float* __restrict__ bv,
                              float* __restrict__ qb, float* __restrict__ vb) {
    __shared__ float As[16][132];
    __shared__ float Ws[16][132];
    int tid = threadIdx.x;
    long rowBase = (long)blockIdx.y * 128;
    int colBase = blockIdx.x * 128;
    int tr = tid >> 4, tc = tid & 15;
    int lrow = tid >> 2;
    int lkq = tid & 3;
    const int D = 256;
    float acc[8][8];
    #pragma unroll
    for (int i = 0; i < 8; i++)
        #pragma unroll
        for (int j = 0; j < 8; j++) acc[i][j] = 0.f;

    for (int k0 = 0; k0 < D; k0 += 16) {
        #pragma unroll
        for (int half = 0; half < 2; half++) {
            int row = lrow + 64 * half;
            int kc = k0 + lkq * 4;
            float4 av = *(const float4*)(xx + (rowBase + row) * D + kc);
            float4 pv = *(const float4*)(pos + (rowBase + row) * D + kc);
            As[lkq * 4 + 0][row] = av.x + pv.x;
            As[lkq * 4 + 1][row] = av.y + pv.y;
            As[lkq * 4 + 2][row] = av.z + pv.z;
            As[lkq * 4 + 3][row] = av.w + pv.w;
            int ocol = colBase + row;
            const float* Wp = (ocol < 256) ? (wqk + (long)ocol * D) : (wv + (long)(ocol - 256) * D);
            float4 wvv = *(const float4*)(Wp + kc);
            Ws[lkq * 4 + 0][row] = wvv.x;
            Ws[lkq * 4 + 1][row] = wvv.y;
            Ws[lkq * 4 + 2][row] = wvv.z;
            Ws[lkq * 4 + 3][row] = wvv.w;
        }
        __syncthreads();
        #pragma unroll
        for (int kk = 0; kk < 16; kk++) {
            float a[8], w[8];
            *(float4*)(a + 0) = *(const float4*)&As[kk][tr * 8 + 0];
            *(float4*)(a + 4) = *(const float4*)&As[kk][tr * 8 + 4];
            *(float4*)(w + 0) = *(const float4*)&Ws[kk][tc * 8 + 0];
            *(float4*)(w + 4) = *(const float4*)&Ws[kk][tc * 8 + 4];
            #pragma unroll
            for (int i = 0; i < 8; i++)
                #pragma unroll
                for (int j = 0; j < 8; j++)
                    acc[i][j] += a[i] * w[j];
        }
        __syncthreads();
    }
    int col0 = colBase + tc * 8;
    #pragma unroll
    for (int i = 0; i < 8; i++) {
        long row = rowBase + tr * 8 + i;
        if (col0 < 256) {
            float4 v0 = make_float4(acc[i][0], acc[i][1], acc[i][2], acc[i][3]);
            float4 v1 = make_float4(acc[i][4], acc[i][5], acc[i][6], acc[i][7]);
            *(float4*)(qb + row * 256 + col0) = v0;
            *(float4*)(qb + row * 256 + col0 + 4) = v1;
        } else {
            int cc = col0 - 256;
            float4 v0 = make_float4(acc[i][0] + bv[cc + 0], acc[i][1] + bv[cc + 1],
                                    acc[i][2] + bv[cc + 2], acc[i][3] + bv[cc + 3]);
            float4 v1 = make_float4(acc[i][4] + bv[cc + 4], acc[i][5] + bv[cc + 5],
                                    acc[i][6] + bv[cc + 6], acc[i][7] + bv[cc + 7]);
            *(float4*)(vb + row * 256 + cc) = v0;
            *(float4*)(vb + row * 256 + cc + 4) = v1;
        }
    }
}

__global__ void gram_kernel(const float* __restrict__ Q, float* __restrict__ A) {
    int bh = blockIdx.z; int b = bh >> 2; int h = bh & 3;
    int i0 = blockIdx.y * 16, j0 = blockIdx.x * 16;
    __shared__ float Qi[16][65];
    __shared__ float Qj[16][65];
    int tid = threadIdx.x;
    for (int e = tid; e < 1024; e += 256) {
        int r = e >> 6, d = e & 63;
        int i = i0 + r;
        Qi[r][d] = Q[((long)b * 256 + h * 64 + (i >> 2)) * 256 + (i & 3) * 64 + d];
        Qj[r][d] = Q[((long)b * 256 + j0 + r) * 256 + h * 64 + d];
    }
    __syncthreads();
    int ti = tid >> 4, tj = tid & 15;
    float acc = 0.f;
    #pragma unroll
    for (int d = 0; d < 64; d++) acc += Qi[ti][d] * Qj[tj][d];
    A[((long)bh * 256 + (i0 + ti)) * 256 + (j0 + tj)] = acc;
}

__global__ void softmax_row_kernel(float* __restrict__ A) {
    __shared__ float red[256];
    long row = blockIdx.x;
    float* p = A + row * 256;
    int t = threadIdx.x;
    float v = p[t];
    red[t] = v; __syncthreads();
    for (int s = 128; s > 0; s >>= 1) { if (t < s) red[t] = fmaxf(red[t], red[t + s]); __syncthreads(); }
    float m = red[0]; __syncthreads();
    float e = expf(v - m);
    red[t] = e; __syncthreads();
    for (int s = 128; s > 0; s >>= 1) { if (t < s) red[t] += red[t + s]; __syncthreads(); }
    p[t] = e / red[0];
}

// fused: column softmax (over j, per head) at column i + XR = V @ A2 + (xp - xr)
// block per (b, i); 256 threads. writes xrb = xx + pos - xr.
__global__ void colsm_xr_kernel(const float* __restrict__ attn, const float* __restrict__ V,
                                const float* __restrict__ xx, const float* __restrict__ pos,
                                float* __restrict__ xrb) {
    int b = blockIdx.x >> 8;
    int i = blockIdx.x & 255;
    int t = threadIdx.x;
    __shared__ float colv[4][256];
    __shared__ float4 r4[256];
    #pragma unroll
    for (int h = 0; h < 4; h++)
        colv[h][t] = attn[(((long)(b * 4 + h)) * 256 + t) * 256 + i];
    float4 vm = make_float4(colv[0][t], colv[1][t], colv[2][t], colv[3][t]);
    r4[t] = vm;
    __syncthreads();
    for (int s = 128; s > 0; s >>= 1) {
        if (t < s) {
            float4 o = r4[t + s];
            r4[t].x = fmaxf(r4[t].x, o.x); r4[t].y = fmaxf(r4[t].y, o.y);
            r4[t].z = fmaxf(r4[t].z, o.z); r4[t].w = fmaxf(r4[t].w, o.w);
        }
        __syncthreads();
    }
    float4 mx = r4[0];
    __syncthreads();
    float4 ev = make_float4(expf(vm.x - mx.x), expf(vm.y - mx.y),
                            expf(vm.z - mx.z), expf(vm.w - mx.w));
    r4[t] = ev;
    __syncthreads();
    for (int s = 128; s > 0; s >>= 1) {
        if (t < s) {
            float4 o = r4[t + s];
            r4[t].x += o.x; r4[t].y += o.y; r4[t].z += o.z; r4[t].w += o.w;
        }
        __syncthreads();
    }
    float4 sm = r4[0];
    __syncthreads();
    colv[0][t] = ev.x / sm.x;
    colv[1][t] = ev.y / sm.y;
    colv[2][t] = ev.z / sm.z;
    colv[3][t] = ev.w / sm.w;
    __syncthreads();
    int c = t; int h = c >> 6;
    const float* vp = V + ((long)b * 256) * 256 + c;
    float acc = 0.f;
    #pragma unroll 8
    for (int j = 0; j < 256; j++) acc += vp[(long)j * 256] * colv[h][j];
    long row = (long)b * 256 + i;
    xrb[row * 256 + c] = xx[row * 256 + c] + pos[row * 256 + c] - acc;
}

// xx = (xx + pos) + relu(bn(qb));  cat[.., layer*256+c] = xx
__global__ void addcat_bn_kernel(const float* __restrict__ qb, float* __restrict__ xx,
                                 const float* __restrict__ pos, float* __restrict__ cat,
                                 int layer) {
    int t = blockIdx.x * 256 + threadIdx.x;
    int c = t & 255; int row = t >> 8;
    float y = fmaxf((qb[t] - g_m1[c]) * g_i1[c], 0.f);
    float v = xx[t] + pos[t] + y;
    xx[t] = v;
    cat[(long)row * 1280 + layer * 256 + c] = v;
}

// ----------------------------------------------------------------------------
// Host orchestration
// ----------------------------------------------------------------------------
static void gemm_old(const float* A, const float* W, const float* bias, float* C,
                     int R, int D, int O) {
    dim3 grid(CEILDIV(O, 64), CEILDIV(R, 64));
    gemm_kernel<<<grid, 256>>>(A, W, bias, C, R, D, O);
}

static void gemm_big(const float* A, const float* W, const float* bias, float* C,
                     int R, int D, int O, int useStats) {
    dim3 grid(CEILDIV(O, 128), R / 128);
    gemm128_kernel<<<grid, 256>>>(A, W, bias, C, R, D, O, useStats);
}

static void computeStats(const float* X, int R, int C) {
    zero_stats_kernel<<<1, 1024>>>();
    int rpb = CEILDIV(R, 120);
    int grid = CEILDIV(R, rpb);
    stats_kernel<<<grid, 256>>>(X, R, C, rpb);
    finalize1_kernel<<<CEILDIV(C, 256), 256>>>(C, R);
}

static void bn(float* X, int R, int C, int act) {
    computeStats(X, R, C);
    long total = (long)R * C;
    bn_apply_kernel<<<(int)CEILDIV(total, 256), 256>>>(X, total, C, act);
}

extern "C" void kernel_launch(void* const* d_in, const int* in_sizes, int n_in,
                              void* d_out, int out_size) {
    const float* x       = (const float*)d_in[0];
    const float* conv1_w = (const float*)d_in[1];
    const float* conv2_w = (const float*)d_in[2];
    const float* g0_w1   = (const float*)d_in[3];
    const float* g0_w2   = (const float*)d_in[4];
    const float* g0_wc   = (const float*)d_in[5];
    const float* g1_w1   = (const float*)d_in[6];
    const float* g1_w2   = (const float*)d_in[7];
    const float* g1_wc   = (const float*)d_in[8];
    const float* pt_w    = (const float*)d_in[9];
    const float* pos_w   = (const float*)d_in[10];
    const float* pos_b   = (const float*)d_in[11];
    const float* sa_wqk  = (const float*)d_in[12];
    const float* sa_wv   = (const float*)d_in[13];
    const float* sa_bv   = (const float*)d_in[14];
    const float* sa_wt   = (const float*)d_in[15];
    const float* sa_bt   = (const float*)d_in[16];
    const float* fuse_w  = (const float*)d_in[17];
    const float* lin1_w  = (const float*)d_in[18];
    const float* lin2_w  = (const float*)d_in[19];
    const float* lin2_b  = (const float*)d_in[20];
    const float* lin3_w  = (const float*)d_in[21];
    const float* lin3_b  = (const float*)d_in[22];
    float* out = (float*)d_out;

    float *xyz, *h1, *points, *newxyz, *newxyz2, *newpts, *Ub, *Vb, *w1a, *w1d, *pool, *f0, *f1;
    float *pos, *xx, *qb, *vb, *xrb, *attn, *catb, *fuseb, *gmax, *l1, *l2;
    int *fpsidx, *knn, *knn2;
    cudaGetSymbolAddress((void**)&xyz, g_xyz);
    cudaGetSymbolAddress((void**)&h1, g_h1);
    cudaGetSymbolAddress((void**)&points, g_points);
    cudaGetSymbolAddress((void**)&fpsidx, g_fpsidx);
    cudaGetSymbolAddress((void**)&newxyz, g_newxyz);
    cudaGetSymbolAddress((void**)&newxyz2, g_newxyz2);
    cudaGetSymbolAddress((void**)&newpts, g_newpts);
    cudaGetSymbolAddress((void**)&knn, g_knn);
    cudaGetSymbolAddress((void**)&knn2, g_knn2);
    cudaGetSymbolAddress((void**)&Ub, g_U);
    cudaGetSymbolAddress((void**)&Vb, g_V);
    cudaGetSymbolAddress((void**)&w1a, g_w1a);
    cudaGetSymbolAddress((void**)&w1d, g_w1d);
    cudaGetSymbolAddress((void**)&pool, g_pool);
    cudaGetSymbolAddress((void**)&f0, g_f0);
    cudaGetSymbolAddress((void**)&f1, g_f1);
    cudaGetSymbolAddress((void**)&pos, g_pos);
    cudaGetSymbolAddress((void**)&xx, g_x);
    cudaGetSymbolAddress((void**)&qb, g_q);
    cudaGetSymbolAddress((void**)&vb, g_v);
    cudaGetSymbolAddress((void**)&xrb, g_xr);
    cudaGetSymbolAddress((void**)&attn, g_attn);
    cudaGetSymbolAddress((void**)&catb, g_cat);
    cudaGetSymbolAddress((void**)&fuseb, g_fuse);
    cudaGetSymbolAddress((void**)&gmax, g_gmax);
    cudaGetSymbolAddress((void**)&l1, g_l1);
    cudaGetSymbolAddress((void**)&l2, g_l2);

    // ---- Stage A ----
    transpose_x_kernel<<<CEILDIV(8*2048*3, 256), 256>>>(x, xyz);
    gemm_old(xyz, conv1_w, nullptr, h1, 16384, 3, 64);
    computeStats(h1, 16384, 64);
    gemm_big(h1, conv2_w, nullptr, points, 16384, 64, 64, 1);
    bn(points, 16384, 64, 0);

    // ---- Stage B: FPS(512) + gathers; kNN1 co-launched with FPS2; kNN2 to
    // its OWN buffer (g_knn2) so stage-1 lists survive until Stage C ----
    fps_kernel<<<8, 1024>>>(xyz, 2048, 512, fpsidx);
    gather_kernel<<<CEILDIV(8*512*3, 256), 256>>>(xyz, fpsidx, newxyz, 512, 2048, 3, 8L*512*3);
    gather_kernel<<<CEILDIV(8*512*64, 256), 256>>>(points, fpsidx, newpts, 512, 2048, 64, 8L*512*64);
    knn_fps_kernel<<<4096 + 8, 256>>>(newxyz, xyz, 512, 2048, knn, 4096,
                                      newxyz, 512, 256, fpsidx);
    gather_kernel<<<CEILDIV(8*256*3, 256), 256>>>(newxyz, fpsidx, newxyz2, 256, 512, 3, 8L*256*3);
    knn_kernel<<<2048, 256>>>(newxyz2, newxyz, 256, 512, knn2);

    // ---- Stage C: local_op 0 via U/V ----
    {
        split_w1_kernel<<<CEILDIV(128*64, 256), 256>>>(g0_w1, w1a, w1d, 128, 64, 128*64);
        gemm_big(points, w1a, nullptr, Ub, 16384, 64, 128, 0);
        gemm_big(newpts, w1d, nullptr, Vb, 4096, 64, 128, 0);
        const int ks[3] = {16, 32, 64};
        const int kshift[3] = {4, 5, 6};
        for (int si = 0; si < 3; si++) {
            int k = ks[si];
            int R = 8 * 512 * k;
            zero_stats_kernel<<<1, 1024>>>();
            stats1_kernel<<<256, 128>>>(Ub, Vb, knn, 512, 2048, 128, k, 16);
            finalize1_kernel<<<1, 256>>>(128, R);
            int nBy = R / 128;
            dim3 grid(1, nBy);
            local_gemm2_kernel<<<grid, 256>>>(Ub, Vb, knn, g0_w2, pool,
                                              512, 2048, 128, 128, kshift[si], 384, si * 128);
            reduce_part_kernel<<<128, 256>>>(nBy, 128, R);
            pool_finalize_kernel<<<4096, 128>>>(pool, 384, si * 128);
        }
        gemm_big(pool, g0_wc, nullptr, f0, 4096, 384, 128, 0);
        bn(f0, 4096, 128, 0);
    }

    // ---- Stage D gather for stage E ----
    gather_kernel<<<CEILDIV(8*256*128, 256), 256>>>(f0, fpsidx, newpts, 256, 512, 128, 8L*256*128);

    // ---- Stage E: local_op 1 via U/V ----
    {
        split_w1_kernel<<<CEILDIV(256*128, 256), 256>>>(g1_w1, w1a, w1d, 256, 128, 256*128);
        gemm_big(f0, w1a, nullptr, Ub, 4096, 128, 256, 0);
        gemm_big(newpts, w1d, nullptr, Vb, 2048, 128, 256, 0);
        const int ks[3] = {16, 32, 64};
        const int kshift[3] = {4, 5, 6};
        for (int si = 0; si < 3; si++) {
            int k = ks[si];
            int R = 8 * 256 * k;
            zero_stats_kernel<<<1, 1024>>>();
            stats1_kernel<<<128, 256>>>(Ub, Vb, knn2, 256, 512, 256, k, 16);
            finalize1_kernel<<<1, 256>>>(256, R);
            int nBy = R / 128;
            dim3 grid(2, nBy);
            local_gemm2_kernel<<<grid, 256>>>(Ub, Vb, knn2, g1_w2, pool,
                                              256, 512, 256, 256, kshift[si], 768, si * 256);
            reduce_part_kernel<<<256, 256>>>(nBy, 256, R);
            pool_finalize_kernel<<<2048, 256>>>(pool, 768, si * 256);
        }
        gemm_big(pool, g1_wc, nullptr, f1, 2048, 768, 256, 0);
        bn(f1, 2048, 256, 0);
    }

    // ---- Stage F ----
    gemm_old(newxyz2, pos_w, pos_b, pos, 2048, 3, 256);
    gemm_big(f1, pt_w, nullptr, xx, 2048, 256, 256, 0);
    bn(xx, 2048, 256, 0);

    // ---- Stage G: 4 offset self-attention layers ----
    for (int i = 0; i < 4; i++) {
        gemmqv_kernel<<<dim3(4, 16), 256>>>(xx, pos,
                                            sa_wqk + (long)i * 256 * 256,
                                            sa_wv + (long)i * 256 * 256,
                                            sa_bv + i * 256, qb, vb);
        gram_kernel<<<dim3(16, 16, 32), 256>>>(qb, attn);
        softmax_row_kernel<<<8192, 256>>>(attn);
        colsm_xr_kernel<<<2048, 256>>>(attn, vb, xx, pos, xrb);
        gemm_big(xrb, sa_wt + (long)i * 256 * 256, sa_bt + i * 256, qb, 2048, 256, 256, 0);
        computeStats(qb, 2048, 256);
        addcat_bn_kernel<<<2048, 256>>>(qb, xx, pos, catb, i);
    }
    catf1_kernel<<<2048, 256>>>(f1, catb);

    // ---- Stage H ----
    gemm_big(catb, fuse_w, nullptr, fuseb, 2048, 1280, 1024, 0);
    bn(fuseb, 2048, 1024, 1);
    maxn_kernel<<<dim3(8, 4), 256>>>(fuseb, gmax);
    gemm_old(gmax, lin1_w, nullptr, l1, 8, 1024, 512);
    bn_small_kernel<<<2, 256>>>(l1, 512, 0.2f);
    gemm_old(l1, lin2_w, lin2_b, l2, 8, 512, 256);
    bn_small_kernel<<<1, 256>>>(l2, 256, 0.2f);
    gemm_old(l2, lin3_w, lin3_b, out, 8, 256, 40);
}